// round 8
// baseline (speedup 1.0000x reference)
#include <cuda_runtime.h>
#include <cuda_bf16.h>
#include <math.h>
#include <stdint.h>

#define NMAX 100000
#define EMAX 1600000
#define DDIM 128

// ---------------- scratch (static __device__ arrays; no allocation) ----------
__device__ float g_h [NMAX * DDIM];
__device__ float g_x2[NMAX * DDIM];
__device__ float g_u [NMAX * DDIM];
__device__ float g_v [NMAX * DDIM];
__device__ __nv_bfloat16 g_ahi[NMAX * DDIM];
__device__ __nv_bfloat16 g_alo[NMAX * DDIM];
__device__ __nv_bfloat16 g_wthi[4 * DDIM * DDIM];
__device__ __nv_bfloat16 g_wtlo[4 * DDIM * DDIM];
__device__ float4 g_asrc[NMAX];
__device__ float4 g_adst[NMAX];
__device__ float4 g_ew  [EMAX];
__device__ int g_deg   [NMAX];
__device__ int g_rowptr[NMAX + 1];
__device__ int g_cursor[NMAX];
__device__ int g_col   [EMAX];
__device__ int g_bsums [1024];

__device__ __forceinline__ uint32_t smem_to_u32(const void* p) {
    uint32_t a;
    asm("{ .reg .u64 t; cvta.to.shared.u64 t, %1; cvt.u32.u64 %0, t; }" : "=r"(a) : "l"(p));
    return a;
}
#define SW128(off) ((off) ^ (((off) >> 3) & 0x70))

#define LDSM4(r0, r1, r2, r3, addr) \
    asm volatile("ldmatrix.sync.aligned.m8n8.x4.shared.b16 {%0,%1,%2,%3}, [%4];" \
        : "=r"(r0), "=r"(r1), "=r"(r2), "=r"(r3) : "r"(addr))

__device__ __forceinline__ void mma16816(float* d, const uint32_t* a, const uint32_t* b) {
    asm volatile(
        "mma.sync.aligned.m16n8k16.row.col.f32.bf16.bf16.f32 "
        "{%0,%1,%2,%3},{%4,%5,%6,%7},{%8,%9},{%0,%1,%2,%3};"
        : "+f"(d[0]), "+f"(d[1]), "+f"(d[2]), "+f"(d[3])
        : "r"(a[0]), "r"(a[1]), "r"(a[2]), "r"(a[3]), "r"(b[0]), "r"(b[1]));
}

// ---------------- weight splits (main stream) ----------------
__device__ __forceinline__ void wsplit_one(const float* __restrict__ W,
                                           __nv_bfloat16* __restrict__ hi,
                                           __nv_bfloat16* __restrict__ lo, int i) {
    int nn = i >> 6;
    int kp = (i & 63) * 2;
    float x0 = W[(size_t)kp * 128 + nn];
    float x1 = W[(size_t)(kp + 1) * 128 + nn];
    __nv_bfloat162 h = __floats2bfloat162_rn(x0, x1);
    float r0 = x0 - __bfloat162float(h.x);
    float r1 = x1 - __bfloat162float(h.y);
    __nv_bfloat162 l = __floats2bfloat162_rn(r0, r1);
    reinterpret_cast<__nv_bfloat162*>(hi)[i] = h;
    reinterpret_cast<__nv_bfloat162*>(lo)[i] = l;
}

__global__ void k_wsplit_all(const float* __restrict__ W1, const float* __restrict__ W2,
                             const float* __restrict__ lpw1,
                             __nv_bfloat16* __restrict__ wthi, __nv_bfloat16* __restrict__ wtlo) {
    const int WSZ = DDIM * DDIM;
    int i = blockIdx.x * blockDim.x + threadIdx.x;
    if (i < 8192)       wsplit_one(W1,               wthi + 0 * WSZ, wtlo + 0 * WSZ, i);
    else if (i < 16384) wsplit_one(W2,               wthi + 1 * WSZ, wtlo + 1 * WSZ, i - 8192);
    else if (i < 24576) wsplit_one(lpw1,             wthi + 2 * WSZ, wtlo + 2 * WSZ, i - 16384);
    else                wsplit_one(lpw1 + 128 * 128, wthi + 3 * WSZ, wtlo + 3 * WSZ, i - 24576);
}

// ---------------- CSR build (side stream) ----------------
__global__ void k_zero_deg(int n) {
    int i = blockIdx.x * blockDim.x + threadIdx.x;
    if (i < n) g_deg[i] = 0;
}
__global__ void k_hist(const int* __restrict__ dst, int e) {
    int i = blockIdx.x * blockDim.x + threadIdx.x;
    if (i < e) atomicAdd(&g_deg[dst[i]], 1);
}
__global__ void k_scan1(int n) {
    __shared__ int sm[1024];
    int tid = threadIdx.x;
    int i = blockIdx.x * 1024 + tid;
    int v = (i < n) ? g_deg[i] : 0;
    sm[tid] = v;
    __syncthreads();
    for (int off = 1; off < 1024; off <<= 1) {
        int t = (tid >= off) ? sm[tid - off] : 0;
        __syncthreads();
        sm[tid] += t;
        __syncthreads();
    }
    if (i < n) g_rowptr[i] = sm[tid] - v;
    if (tid == 1023) g_bsums[blockIdx.x] = sm[1023];
}
__global__ void k_scan2(int nb) {       // nb <= 128
    __shared__ int wsum[4];
    int tid = threadIdx.x;              // 128 threads
    int lane = tid & 31, w = tid >> 5;
    int v = (tid < nb) ? g_bsums[tid] : 0;
    int x = v;
#pragma unroll
    for (int o = 1; o < 32; o <<= 1) {
        int t = __shfl_up_sync(0xffffffffu, x, o);
        if (lane >= o) x += t;
    }
    if (lane == 31) wsum[w] = x;
    __syncthreads();
    int add = 0;
#pragma unroll
    for (int j = 0; j < 4; j++) add += (j < w) ? wsum[j] : 0;
    if (tid < nb) g_bsums[tid] = x - v + add;   // exclusive
}
__global__ void k_scan3(int n, int e) {
    int i = blockIdx.x * 1024 + threadIdx.x;
    if (i < n) {
        int v = g_rowptr[i] + g_bsums[blockIdx.x];
        g_rowptr[i] = v;
        g_cursor[i] = v;
    }
    if (i == 0) g_rowptr[n] = e;
}
__global__ void k_scatter(const int* __restrict__ src, const int* __restrict__ dst, int e) {
    int i = blockIdx.x * blockDim.x + threadIdx.x;
    if (i < e) {
        int d = dst[i];
        int slot = atomicAdd(&g_cursor[d], 1);
        g_col[slot] = src[i];
    }
}

// ---------------- HMMA GEMM + fused alpha ----------------
#define GEMM_SMEM 131072

__global__ void __launch_bounds__(512, 1) k_gemm_mma(
    const float* __restrict__ Af,
    const __nv_bfloat16* __restrict__ Ahi, const __nv_bfloat16* __restrict__ Alo,
    const __nv_bfloat16* __restrict__ Bhi, const __nv_bfloat16* __restrict__ Blo,
    float* __restrict__ C,
    const float* __restrict__ a_src, const float* __restrict__ a_dst, int n)
{
    extern __shared__ char smem[];
    __shared__ float sAl[128][4];
    __shared__ float sDl[128][4];
    uint32_t sb = smem_to_u32(smem);
    const uint32_t sAhi = sb;
    const uint32_t sAlo = sb + 32768;
    const uint32_t sBhi = sb + 65536;
    const uint32_t sBlo = sb + 98304;

    int tid = threadIdx.x;
    int wid = tid >> 5, lane = tid & 31;
    int wm = wid & 3, wn = wid >> 2;
    int row0 = blockIdx.x * 128;

    if (a_src && tid < 128) {
        *reinterpret_cast<float4*>(&sAl[tid][0]) = make_float4(0.f, 0.f, 0.f, 0.f);
        *reinterpret_cast<float4*>(&sDl[tid][0]) = make_float4(0.f, 0.f, 0.f, 0.f);
    }

    float acc[2][4][4];
#pragma unroll
    for (int i = 0; i < 2; i++)
#pragma unroll
        for (int j = 0; j < 4; j++)
#pragma unroll
            for (int q = 0; q < 4; q++) acc[i][j][q] = 0.f;

    const uint4 zero4 = make_uint4(0, 0, 0, 0);

#pragma unroll
    for (int t = 0; t < 4; t++) {
        int i = tid + t * 512;
        int r = i >> 4;
        int o = i & 15;
        int kh = o >> 3, oo = o & 7;
        uint32_t soff = (uint32_t)(kh * 16384) + SW128((uint32_t)(r * 128 + oo * 16));
        size_t elem = (size_t)(row0 + r) * 128 + kh * 64 + oo * 8;
        size_t bidx = ((size_t)r * 128 + kh * 64 + oo * 8) >> 3;
        bool av = (row0 + r) < n;
        uint4 va, vb;
        if (Af) {
            float4 f0 = make_float4(0.f, 0.f, 0.f, 0.f), f1 = f0;
            if (av) {
                f0 = *reinterpret_cast<const float4*>(&Af[elem]);
                f1 = *reinterpret_cast<const float4*>(&Af[elem + 4]);
            }
            __nv_bfloat162 h0 = __floats2bfloat162_rn(f0.x, f0.y);
            __nv_bfloat162 h1 = __floats2bfloat162_rn(f0.z, f0.w);
            __nv_bfloat162 h2 = __floats2bfloat162_rn(f1.x, f1.y);
            __nv_bfloat162 h3 = __floats2bfloat162_rn(f1.z, f1.w);
            __nv_bfloat162 l0 = __floats2bfloat162_rn(f0.x - __bfloat162float(h0.x), f0.y - __bfloat162float(h0.y));
            __nv_bfloat162 l1 = __floats2bfloat162_rn(f0.z - __bfloat162float(h1.x), f0.w - __bfloat162float(h1.y));
            __nv_bfloat162 l2 = __floats2bfloat162_rn(f1.x - __bfloat162float(h2.x), f1.y - __bfloat162float(h2.y));
            __nv_bfloat162 l3 = __floats2bfloat162_rn(f1.z - __bfloat162float(h3.x), f1.w - __bfloat162float(h3.y));
            va = make_uint4(*(uint32_t*)&h0, *(uint32_t*)&h1, *(uint32_t*)&h2, *(uint32_t*)&h3);
            vb = make_uint4(*(uint32_t*)&l0, *(uint32_t*)&l1, *(uint32_t*)&l2, *(uint32_t*)&l3);
        } else {
            va = av ? reinterpret_cast<const uint4*>(Ahi)[elem >> 3] : zero4;
            vb = av ? reinterpret_cast<const uint4*>(Alo)[elem >> 3] : zero4;
        }
        uint4 wh = reinterpret_cast<const uint4*>(Bhi)[bidx];
        uint4 wl = reinterpret_cast<const uint4*>(Blo)[bidx];
        *reinterpret_cast<uint4*>(smem + (sAhi - sb) + soff) = va;
        *reinterpret_cast<uint4*>(smem + (sAlo - sb) + soff) = vb;
        *reinterpret_cast<uint4*>(smem + (sBhi - sb) + soff) = wh;
        *reinterpret_cast<uint4*>(smem + (sBlo - sb) + soff) = wl;
    }
    __syncthreads();

#pragma unroll
    for (int kh = 0; kh < 2; kh++) {
        uint32_t hoff = (uint32_t)(kh * 16384);
#pragma unroll
        for (int kk = 0; kk < 4; kk++) {
            int lr = lane & 15;
            int kin = kk * 16 + ((lane >> 4) << 3);
            uint32_t ahi[2][4], alo[2][4], bxh[2][4], bxl[2][4];
#pragma unroll
            for (int mf = 0; mf < 2; mf++) {
                uint32_t off = hoff + SW128((uint32_t)((wm * 32 + mf * 16 + lr) * 128 + kin * 2));
                LDSM4(ahi[mf][0], ahi[mf][1], ahi[mf][2], ahi[mf][3], sAhi + off);
                LDSM4(alo[mf][0], alo[mf][1], alo[mf][2], alo[mf][3], sAlo + off);
            }
#pragma unroll
            for (int nf = 0; nf < 2; nf++) {
                uint32_t off = hoff + SW128((uint32_t)((wn * 32 + nf * 16 + lr) * 128 + kin * 2));
                LDSM4(bxh[nf][0], bxh[nf][1], bxh[nf][2], bxh[nf][3], sBhi + off);
                LDSM4(bxl[nf][0], bxl[nf][1], bxl[nf][2], bxl[nf][3], sBlo + off);
            }
#pragma unroll
            for (int mf = 0; mf < 2; mf++) {
#pragma unroll
                for (int ns = 0; ns < 4; ns++) {
                    int g = ns >> 1, od = ns & 1;
                    uint32_t bh[2] = { bxh[g][od], bxh[g][od + 2] };
                    uint32_t bl[2] = { bxl[g][od], bxl[g][od + 2] };
                    mma16816(acc[mf][ns], ahi[mf], bh);
                    mma16816(acc[mf][ns], ahi[mf], bl);
                    mma16816(acc[mf][ns], alo[mf], bh);
                }
            }
        }
    }

    int qrow = lane >> 2, qcol = (lane & 3) * 2;

    if (a_src) {
        float2 s2[4], d2[4];
#pragma unroll
        for (int ns = 0; ns < 4; ns++) {
            int c = wn * 32 + ns * 8 + qcol;
            s2[ns] = *reinterpret_cast<const float2*>(&a_src[c]);
            d2[ns] = *reinterpret_cast<const float2*>(&a_dst[c]);
        }
#pragma unroll
        for (int mf = 0; mf < 2; mf++) {
            int rl = wm * 32 + mf * 16 + qrow;
            float pa0 = 0.f, pd0 = 0.f, pa1 = 0.f, pd1 = 0.f;
#pragma unroll
            for (int ns = 0; ns < 4; ns++) {
                pa0 += acc[mf][ns][0] * s2[ns].x + acc[mf][ns][1] * s2[ns].y;
                pd0 += acc[mf][ns][0] * d2[ns].x + acc[mf][ns][1] * d2[ns].y;
                pa1 += acc[mf][ns][2] * s2[ns].x + acc[mf][ns][3] * s2[ns].y;
                pd1 += acc[mf][ns][2] * d2[ns].x + acc[mf][ns][3] * d2[ns].y;
            }
            atomicAdd(&sAl[rl][wn], pa0);     atomicAdd(&sDl[rl][wn], pd0);
            atomicAdd(&sAl[rl + 8][wn], pa1); atomicAdd(&sDl[rl + 8][wn], pd1);
        }
    }

#pragma unroll
    for (int mf = 0; mf < 2; mf++) {
#pragma unroll
        for (int ns = 0; ns < 4; ns++) {
            int r0 = row0 + wm * 32 + mf * 16 + qrow;
            int c0 = wn * 32 + ns * 8 + qcol;
            if (r0 < n)
                *reinterpret_cast<float2*>(&C[(size_t)r0 * 128 + c0]) =
                    make_float2(acc[mf][ns][0], acc[mf][ns][1]);
            if (r0 + 8 < n)
                *reinterpret_cast<float2*>(&C[(size_t)(r0 + 8) * 128 + c0]) =
                    make_float2(acc[mf][ns][2], acc[mf][ns][3]);
        }
    }

    if (a_src) {
        __syncthreads();
        if (tid < 128 && row0 + tid < n) {
            g_asrc[row0 + tid] = *reinterpret_cast<float4*>(&sAl[tid][0]);
            g_adst[row0 + tid] = *reinterpret_cast<float4*>(&sDl[tid][0]);
        }
    }
}

// ---------------- dual-B HMMA GEMM ----------------
#define GEMM2_SMEM 196608

__global__ void __launch_bounds__(512, 1) k_gemm_mma2(
    const __nv_bfloat16* __restrict__ Ahi, const __nv_bfloat16* __restrict__ Alo,
    const __nv_bfloat16* __restrict__ B1hi, const __nv_bfloat16* __restrict__ B1lo,
    const __nv_bfloat16* __restrict__ B2hi, const __nv_bfloat16* __restrict__ B2lo,
    float* __restrict__ C1, float* __restrict__ C2, int n)
{
    extern __shared__ char smem[];
    uint32_t sb = smem_to_u32(smem);
    const uint32_t sAhi = sb;
    const uint32_t sAlo = sb + 32768;

    int tid = threadIdx.x;
    int wid = tid >> 5, lane = tid & 31;
    int wm = wid & 3, wn = wid >> 2;
    int row0 = blockIdx.x * 128;

    const uint4 zero4 = make_uint4(0, 0, 0, 0);

#pragma unroll
    for (int t = 0; t < 4; t++) {
        int i = tid + t * 512;
        int r = i >> 4;
        int o = i & 15;
        int kh = o >> 3, oo = o & 7;
        uint32_t soff = (uint32_t)(kh * 16384) + SW128((uint32_t)(r * 128 + oo * 16));
        size_t elem = (size_t)(row0 + r) * 128 + kh * 64 + oo * 8;
        size_t bidx = ((size_t)r * 128 + kh * 64 + oo * 8) >> 3;
        bool av = (row0 + r) < n;
        uint4 va = av ? reinterpret_cast<const uint4*>(Ahi)[elem >> 3] : zero4;
        uint4 vb = av ? reinterpret_cast<const uint4*>(Alo)[elem >> 3] : zero4;
        *reinterpret_cast<uint4*>(smem + 0      + soff) = va;
        *reinterpret_cast<uint4*>(smem + 32768  + soff) = vb;
        *reinterpret_cast<uint4*>(smem + 65536  + soff) = reinterpret_cast<const uint4*>(B1hi)[bidx];
        *reinterpret_cast<uint4*>(smem + 98304  + soff) = reinterpret_cast<const uint4*>(B1lo)[bidx];
        *reinterpret_cast<uint4*>(smem + 131072 + soff) = reinterpret_cast<const uint4*>(B2hi)[bidx];
        *reinterpret_cast<uint4*>(smem + 163840 + soff) = reinterpret_cast<const uint4*>(B2lo)[bidx];
    }
    __syncthreads();

    for (int g = 0; g < 2; g++) {
        uint32_t sBhi = sb + 65536 + (uint32_t)g * 65536;
        uint32_t sBlo = sBhi + 32768;
        float* C = g ? C2 : C1;

        float acc[2][4][4];
#pragma unroll
        for (int i = 0; i < 2; i++)
#pragma unroll
            for (int j = 0; j < 4; j++)
#pragma unroll
                for (int q = 0; q < 4; q++) acc[i][j][q] = 0.f;

#pragma unroll
        for (int kh = 0; kh < 2; kh++) {
            uint32_t hoff = (uint32_t)(kh * 16384);
#pragma unroll
            for (int kk = 0; kk < 4; kk++) {
                int lr = lane & 15;
                int kin = kk * 16 + ((lane >> 4) << 3);
                uint32_t ahi[2][4], alo[2][4], bxh[2][4], bxl[2][4];
#pragma unroll
                for (int mf = 0; mf < 2; mf++) {
                    uint32_t off = hoff + SW128((uint32_t)((wm * 32 + mf * 16 + lr) * 128 + kin * 2));
                    LDSM4(ahi[mf][0], ahi[mf][1], ahi[mf][2], ahi[mf][3], sAhi + off);
                    LDSM4(alo[mf][0], alo[mf][1], alo[mf][2], alo[mf][3], sAlo + off);
                }
#pragma unroll
                for (int nf = 0; nf < 2; nf++) {
                    uint32_t off = hoff + SW128((uint32_t)((wn * 32 + nf * 16 + lr) * 128 + kin * 2));
                    LDSM4(bxh[nf][0], bxh[nf][1], bxh[nf][2], bxh[nf][3], sBhi + off);
                    LDSM4(bxl[nf][0], bxl[nf][1], bxl[nf][2], bxl[nf][3], sBlo + off);
                }
#pragma unroll
                for (int mf = 0; mf < 2; mf++) {
#pragma unroll
                    for (int ns = 0; ns < 4; ns++) {
                        int gg = ns >> 1, od = ns & 1;
                        uint32_t bh[2] = { bxh[gg][od], bxh[gg][od + 2] };
                        uint32_t bl[2] = { bxl[gg][od], bxl[gg][od + 2] };
                        mma16816(acc[mf][ns], ahi[mf], bh);
                        mma16816(acc[mf][ns], ahi[mf], bl);
                        mma16816(acc[mf][ns], alo[mf], bh);
                    }
                }
            }
        }

        int qrow = lane >> 2, qcol = (lane & 3) * 2;
#pragma unroll
        for (int mf = 0; mf < 2; mf++) {
#pragma unroll
            for (int ns = 0; ns < 4; ns++) {
                int r0 = row0 + wm * 32 + mf * 16 + qrow;
                int c0 = wn * 32 + ns * 8 + qcol;
                if (r0 < n)
                    *reinterpret_cast<float2*>(&C[(size_t)r0 * 128 + c0]) =
                        make_float2(acc[mf][ns][0], acc[mf][ns][1]);
                if (r0 + 8 < n)
                    *reinterpret_cast<float2*>(&C[(size_t)(r0 + 8) * 128 + c0]) =
                        make_float2(acc[mf][ns][2], acc[mf][ns][3]);
            }
        }
    }
}

// ---------------- warp helpers ----------------
__device__ __forceinline__ float warp_sum(float v) {
#pragma unroll
    for (int o = 16; o; o >>= 1) v += __shfl_xor_sync(0xffffffffu, v, o);
    return v;
}

// ---------------- fused GAT aggregation + ELU + residual + bf16 split -------
__device__ __forceinline__ float lrelu(float x) { return x >= 0.f ? x : 0.2f * x; }
__device__ __forceinline__ float elu(float x)  { return x > 0.f ? x : expm1f(x); }

__global__ void k_edgeagg(const float* __restrict__ h,
                          const float* __restrict__ xprev,
                          float* __restrict__ xnext,
                          __nv_bfloat16* __restrict__ hi,
                          __nv_bfloat16* __restrict__ lo, int n)
{
    __shared__ int   sidx[8][32];
    __shared__ float4 swt[8][32];

    int w = threadIdx.x >> 5;
    int gw = (blockIdx.x * blockDim.x + threadIdx.x) >> 5;
    int lane = threadIdx.x & 31;
    if (gw >= n) return;

    int base = g_rowptr[gw];
    int deg  = g_rowptr[gw + 1] - base;
    float4 ad = g_adst[gw];

    float s0 = 0.f, s1 = 0.f, s2 = 0.f, s3 = 0.f;
    for (int i = lane; i < deg; i += 32) {
        int s = g_col[base + i];
        float4 as = g_asrc[s];
        float p0 = expf(fminf(lrelu(as.x + ad.x), 75.f));
        float p1 = expf(fminf(lrelu(as.y + ad.y), 75.f));
        float p2 = expf(fminf(lrelu(as.z + ad.z), 75.f));
        float p3 = expf(fminf(lrelu(as.w + ad.w), 75.f));
        g_ew[base + i] = make_float4(p0, p1, p2, p3);
        s0 += p0; s1 += p1; s2 += p2; s3 += p3;
    }
    s0 = warp_sum(s0); s1 = warp_sum(s1); s2 = warp_sum(s2); s3 = warp_sum(s3);
    float i0 = 1.f / (s0 + 1e-10f);
    float i1 = 1.f / (s1 + 1e-10f);
    float i2 = 1.f / (s2 + 1e-10f);
    float i3 = 1.f / (s3 + 1e-10f);

    float4 acc = make_float4(0.f, 0.f, 0.f, 0.f);
    int hsel = lane >> 3;
    for (int bi = 0; bi < deg; bi += 32) {
        int cnt = min(32, deg - bi);
        if (lane < cnt) {
            sidx[w][lane] = g_col[base + bi + lane];
            float4 p = g_ew[base + bi + lane];
            swt[w][lane] = make_float4(p.x * i0, p.y * i1, p.z * i2, p.w * i3);
        }
        __syncwarp();
#pragma unroll 4
        for (int j = 0; j < cnt; j++) {
            int s = sidx[w][j];
            float wj = reinterpret_cast<const float*>(&swt[w][j])[hsel];
            float4 hv = *reinterpret_cast<const float4*>(&h[(size_t)s * 128 + 4 * lane]);
            acc.x += hv.x * wj;
            acc.y += hv.y * wj;
            acc.z += hv.z * wj;
            acc.w += hv.w * wj;
        }
        __syncwarp();
    }

    size_t o = (size_t)gw * 128 + 4 * lane;
    float4 xp = *reinterpret_cast<const float4*>(&xprev[o]);
    float4 v = make_float4(elu(acc.x) + xp.x, elu(acc.y) + xp.y,
                           elu(acc.z) + xp.z, elu(acc.w) + xp.w);
    if (xnext) *reinterpret_cast<float4*>(&xnext[o]) = v;
    if (hi) {
        __nv_bfloat162 h0 = __floats2bfloat162_rn(v.x, v.y);
        __nv_bfloat162 h1 = __floats2bfloat162_rn(v.z, v.w);
        __nv_bfloat162 l0 = __floats2bfloat162_rn(v.x - __bfloat162float(h0.x), v.y - __bfloat162float(h0.y));
        __nv_bfloat162 l1 = __floats2bfloat162_rn(v.z - __bfloat162float(h1.x), v.w - __bfloat162float(h1.y));
        uint2 ph = make_uint2(*(uint32_t*)&h0, *(uint32_t*)&h1);
        uint2 pl = make_uint2(*(uint32_t*)&l0, *(uint32_t*)&l1);
        *reinterpret_cast<uint2*>(&hi[o]) = ph;
        *reinterpret_cast<uint2*>(&lo[o]) = pl;
    }
}

// ---------------- pair epilogue ----------------
__global__ void k_pairs(const int* __restrict__ lsrc, const int* __restrict__ ldst,
                        const float* __restrict__ b1, const float* __restrict__ w2,
                        const float* __restrict__ b2, float* __restrict__ out, int p)
{
    int gw = (blockIdx.x * blockDim.x + threadIdx.x) >> 5;
    int lane = threadIdx.x & 31;
    if (gw >= p) return;
    int k = 4 * lane;
    float4 u = *reinterpret_cast<const float4*>(&g_u[(size_t)lsrc[gw] * 128 + k]);
    float4 v = *reinterpret_cast<const float4*>(&g_v[(size_t)ldst[gw] * 128 + k]);
    float4 b = *reinterpret_cast<const float4*>(&b1[k]);
    float4 w = *reinterpret_cast<const float4*>(&w2[k]);
    float t = fmaxf(u.x + v.x + b.x, 0.f) * w.x
            + fmaxf(u.y + v.y + b.y, 0.f) * w.y
            + fmaxf(u.z + v.z + b.z, 0.f) * w.z
            + fmaxf(u.w + v.w + b.w, 0.f) * w.w;
    t = warp_sum(t);
    if (lane == 0) out[gw] = t + b2[0];
}

// ---------------- driver ----------------
extern "C" void kernel_launch(void* const* d_in, const int* in_sizes, int n_in,
                              void* d_out, int out_size)
{
    const float* embed  = (const float*)d_in[0];
    const float* W1     = (const float*)d_in[1];
    const float* a_src1 = (const float*)d_in[2];
    const float* a_dst1 = (const float*)d_in[3];
    const float* W2     = (const float*)d_in[4];
    const float* a_src2 = (const float*)d_in[5];
    const float* a_dst2 = (const float*)d_in[6];
    const float* lp_w1  = (const float*)d_in[7];
    const float* lp_b1  = (const float*)d_in[8];
    const float* lp_w2  = (const float*)d_in[9];
    const float* lp_b2  = (const float*)d_in[10];
    const int*   eidx   = (const int*)d_in[11];
    const int*   lsrc   = (const int*)d_in[12];
    const int*   ldst   = (const int*)d_in[13];
    float* out = (float*)d_out;

    const int N = in_sizes[0] / DDIM;
    const int E = in_sizes[11] / 2;
    const int P = in_sizes[12];
    const int* esrc = eidx;
    const int* edst = eidx + E;

    float* hbuf; cudaGetSymbolAddress((void**)&hbuf, g_h);
    float* x2;   cudaGetSymbolAddress((void**)&x2,   g_x2);
    float* ub;   cudaGetSymbolAddress((void**)&ub,   g_u);
    float* vb;   cudaGetSymbolAddress((void**)&vb,   g_v);
    __nv_bfloat16* ahi; cudaGetSymbolAddress((void**)&ahi, g_ahi);
    __nv_bfloat16* alo; cudaGetSymbolAddress((void**)&alo, g_alo);
    __nv_bfloat16* wthi; cudaGetSymbolAddress((void**)&wthi, g_wthi);
    __nv_bfloat16* wtlo; cudaGetSymbolAddress((void**)&wtlo, g_wtlo);

    cudaFuncSetAttribute(k_gemm_mma,  cudaFuncAttributeMaxDynamicSharedMemorySize, GEMM_SMEM);
    cudaFuncSetAttribute(k_gemm_mma2, cudaFuncAttributeMaxDynamicSharedMemorySize, GEMM2_SMEM);

    // side stream + fork/join events (created once, on the uncaptured
    // correctness call; the captured work is identical on every call)
    static cudaStream_t sB = nullptr;
    static cudaEvent_t evFork = nullptr, evJoin = nullptr;
    if (!sB) {
        cudaStreamCreateWithFlags(&sB, cudaStreamNonBlocking);
        cudaEventCreateWithFlags(&evFork, cudaEventDisableTiming);
        cudaEventCreateWithFlags(&evJoin, cudaEventDisableTiming);
    }

    const int T = 256;
    int nbN  = (N + T - 1) / T;
    int nbE  = (E + T - 1) / T;
    int nbS  = (N + 1023) / 1024;
    int nbW  = (N * 32 + T - 1) / T;
    int nbPW = (P * 32 + T - 1) / T;
    int nbG  = (N + 127) / 128;
    const int WSZ = DDIM * DDIM;

    // fork: CSR build on side stream, concurrent with wsplit + GEMM1
    cudaEventRecord(evFork, 0);
    cudaStreamWaitEvent(sB, evFork, 0);
    k_zero_deg<<<nbN, T, 0, sB>>>(N);
    k_hist<<<nbE, T, 0, sB>>>(edst, E);
    k_scan1<<<nbS, 1024, 0, sB>>>(N);
    k_scan2<<<1, 128, 0, sB>>>(nbS);
    k_scan3<<<nbS, 1024, 0, sB>>>(N, E);
    k_scatter<<<nbE, T, 0, sB>>>(esrc, edst, E);
    cudaEventRecord(evJoin, sB);

    // main stream: weight splits + layer-1 GEMM (fused alpha)
    k_wsplit_all<<<32768 / T, T>>>(W1, W2, lp_w1, wthi, wtlo);
    k_gemm_mma<<<nbG, 512, GEMM_SMEM>>>(embed, nullptr, nullptr,
                                        wthi + 0 * WSZ, wtlo + 0 * WSZ, hbuf,
                                        a_src1, a_dst1, N);

    // join: edgeagg needs CSR
    cudaStreamWaitEvent(0, evJoin, 0);
    k_edgeagg<<<nbW, T>>>(hbuf, embed, x2, ahi, alo, N);

    // layer 2
    k_gemm_mma<<<nbG, 512, GEMM_SMEM>>>(nullptr, ahi, alo,
                                        wthi + 1 * WSZ, wtlo + 1 * WSZ, hbuf,
                                        a_src2, a_dst2, N);
    k_edgeagg<<<nbW, T>>>(hbuf, x2, nullptr, ahi, alo, N);

    // link predictor
    k_gemm_mma2<<<nbG, 512, GEMM2_SMEM>>>(ahi, alo,
                                          wthi + 2 * WSZ, wtlo + 2 * WSZ,
                                          wthi + 3 * WSZ, wtlo + 3 * WSZ,
                                          ub, vb, N);
    k_pairs<<<nbPW, T>>>(lsrc, ldst, lp_b1, lp_w2, lp_b2, out, P);
}

// round 9
// speedup vs baseline: 1.0771x; 1.0771x over previous
#include <cuda_runtime.h>
#include <cuda_bf16.h>
#include <cuda_fp16.h>
#include <math.h>
#include <stdint.h>

#define NMAX 100000
#define EMAX 1600000
#define DDIM 128

// ---------------- scratch ----------------
__device__ __half g_h [NMAX * DDIM];          // fp16 transformed features
__device__ float g_x2[NMAX * DDIM];
__device__ float g_u [NMAX * DDIM];
__device__ float g_v [NMAX * DDIM];
__device__ __nv_bfloat16 g_ahi[NMAX * DDIM];
__device__ __nv_bfloat16 g_alo[NMAX * DDIM];
__device__ __nv_bfloat16 g_wthi[4 * DDIM * DDIM];
__device__ __nv_bfloat16 g_wtlo[4 * DDIM * DDIM];
__device__ float4 g_asrc[NMAX];
__device__ float4 g_adst[NMAX];
__device__ float4 g_ew  [EMAX];
__device__ int g_deg   [NMAX];
__device__ int g_rowptr[NMAX + 1];
__device__ int g_cursor[NMAX];
__device__ int g_col   [EMAX];
__device__ int g_bsums [1024];

__device__ __forceinline__ uint32_t smem_to_u32(const void* p) {
    uint32_t a;
    asm("{ .reg .u64 t; cvta.to.shared.u64 t, %1; cvt.u32.u64 %0, t; }" : "=r"(a) : "l"(p));
    return a;
}
#define SW128(off) ((off) ^ (((off) >> 3) & 0x70))

#define LDSM4(r0, r1, r2, r3, addr) \
    asm volatile("ldmatrix.sync.aligned.m8n8.x4.shared.b16 {%0,%1,%2,%3}, [%4];" \
        : "=r"(r0), "=r"(r1), "=r"(r2), "=r"(r3) : "r"(addr))

__device__ __forceinline__ void mma16816(float* d, const uint32_t* a, const uint32_t* b) {
    asm volatile(
        "mma.sync.aligned.m16n8k16.row.col.f32.bf16.bf16.f32 "
        "{%0,%1,%2,%3},{%4,%5,%6,%7},{%8,%9},{%0,%1,%2,%3};"
        : "+f"(d[0]), "+f"(d[1]), "+f"(d[2]), "+f"(d[3])
        : "r"(a[0]), "r"(a[1]), "r"(a[2]), "r"(a[3]), "r"(b[0]), "r"(b[1]));
}

// ---------------- setup: zero degrees + all 4 weight splits ----------------
__device__ __forceinline__ void wsplit_one(const float* __restrict__ W,
                                           __nv_bfloat16* __restrict__ hi,
                                           __nv_bfloat16* __restrict__ lo, int i) {
    int nn = i >> 6;
    int kp = (i & 63) * 2;
    float x0 = W[(size_t)kp * 128 + nn];
    float x1 = W[(size_t)(kp + 1) * 128 + nn];
    __nv_bfloat162 h = __floats2bfloat162_rn(x0, x1);
    float r0 = x0 - __bfloat162float(h.x);
    float r1 = x1 - __bfloat162float(h.y);
    __nv_bfloat162 l = __floats2bfloat162_rn(r0, r1);
    reinterpret_cast<__nv_bfloat162*>(hi)[i] = h;
    reinterpret_cast<__nv_bfloat162*>(lo)[i] = l;
}

__global__ void k_setup(const float* __restrict__ W1, const float* __restrict__ W2,
                        const float* __restrict__ lpw1,
                        __nv_bfloat16* __restrict__ wthi, __nv_bfloat16* __restrict__ wtlo,
                        int n) {
    const int WSZ = DDIM * DDIM;
    int i = blockIdx.x * blockDim.x + threadIdx.x;
    if (i < n) g_deg[i] = 0;
    if (i < 8192)       wsplit_one(W1,               wthi + 0 * WSZ, wtlo + 0 * WSZ, i);
    else if (i < 16384) wsplit_one(W2,               wthi + 1 * WSZ, wtlo + 1 * WSZ, i - 8192);
    else if (i < 24576) wsplit_one(lpw1,             wthi + 2 * WSZ, wtlo + 2 * WSZ, i - 16384);
    else if (i < 32768) wsplit_one(lpw1 + 128 * 128, wthi + 3 * WSZ, wtlo + 3 * WSZ, i - 24576);
}

// ---------------- CSR build ----------------
__global__ void k_hist(const int* __restrict__ dst, int e) {
    int i = blockIdx.x * blockDim.x + threadIdx.x;
    if (i < e) atomicAdd(&g_deg[dst[i]], 1);
}
__global__ void k_scan1(int n) {
    __shared__ int sm[1024];
    int tid = threadIdx.x;
    int i = blockIdx.x * 1024 + tid;
    int v = (i < n) ? g_deg[i] : 0;
    sm[tid] = v;
    __syncthreads();
    for (int off = 1; off < 1024; off <<= 1) {
        int t = (tid >= off) ? sm[tid - off] : 0;
        __syncthreads();
        sm[tid] += t;
        __syncthreads();
    }
    if (i < n) g_rowptr[i] = sm[tid] - v;
    if (tid == 1023) g_bsums[blockIdx.x] = sm[1023];
}
__global__ void k_scan2(int nb) {       // nb <= 128
    __shared__ int wsum[4];
    int tid = threadIdx.x;
    int lane = tid & 31, w = tid >> 5;
    int v = (tid < nb) ? g_bsums[tid] : 0;
    int x = v;
#pragma unroll
    for (int o = 1; o < 32; o <<= 1) {
        int t = __shfl_up_sync(0xffffffffu, x, o);
        if (lane >= o) x += t;
    }
    if (lane == 31) wsum[w] = x;
    __syncthreads();
    int add = 0;
#pragma unroll
    for (int j = 0; j < 4; j++) add += (j < w) ? wsum[j] : 0;
    if (tid < nb) g_bsums[tid] = x - v + add;
}
__global__ void k_scan3(int n, int e) {
    int i = blockIdx.x * 1024 + threadIdx.x;
    if (i < n) {
        int v = g_rowptr[i] + g_bsums[blockIdx.x];
        g_rowptr[i] = v;
        g_cursor[i] = v;
    }
    if (i == 0) g_rowptr[n] = e;
}
__global__ void k_scatter(const int* __restrict__ src, const int* __restrict__ dst, int e) {
    int i = blockIdx.x * blockDim.x + threadIdx.x;
    if (i < e) {
        int d = dst[i];
        int slot = atomicAdd(&g_cursor[d], 1);
        g_col[slot] = src[i];
    }
}

// ---------------- HMMA GEMM + fused alpha, fp16 h output ----------------
#define GEMM_SMEM 131072

__global__ void __launch_bounds__(512, 1) k_gemm_mma(
    const float* __restrict__ Af,
    const __nv_bfloat16* __restrict__ Ahi, const __nv_bfloat16* __restrict__ Alo,
    const __nv_bfloat16* __restrict__ Bhi, const __nv_bfloat16* __restrict__ Blo,
    __half* __restrict__ C,
    const float* __restrict__ a_src, const float* __restrict__ a_dst, int n)
{
    extern __shared__ char smem[];
    __shared__ float sAl[128][4];
    __shared__ float sDl[128][4];
    uint32_t sb = smem_to_u32(smem);
    const uint32_t sAhi = sb;
    const uint32_t sAlo = sb + 32768;
    const uint32_t sBhi = sb + 65536;
    const uint32_t sBlo = sb + 98304;

    int tid = threadIdx.x;
    int wid = tid >> 5, lane = tid & 31;
    int wm = wid & 3, wn = wid >> 2;
    int row0 = blockIdx.x * 128;

    if (tid < 128) {
        *reinterpret_cast<float4*>(&sAl[tid][0]) = make_float4(0.f, 0.f, 0.f, 0.f);
        *reinterpret_cast<float4*>(&sDl[tid][0]) = make_float4(0.f, 0.f, 0.f, 0.f);
    }

    float acc[2][4][4];
#pragma unroll
    for (int i = 0; i < 2; i++)
#pragma unroll
        for (int j = 0; j < 4; j++)
#pragma unroll
            for (int q = 0; q < 4; q++) acc[i][j][q] = 0.f;

    const uint4 zero4 = make_uint4(0, 0, 0, 0);

#pragma unroll
    for (int t = 0; t < 4; t++) {
        int i = tid + t * 512;
        int r = i >> 4;
        int o = i & 15;
        int kh = o >> 3, oo = o & 7;
        uint32_t soff = (uint32_t)(kh * 16384) + SW128((uint32_t)(r * 128 + oo * 16));
        size_t elem = (size_t)(row0 + r) * 128 + kh * 64 + oo * 8;
        size_t bidx = ((size_t)r * 128 + kh * 64 + oo * 8) >> 3;
        bool av = (row0 + r) < n;
        uint4 va, vb;
        if (Af) {
            float4 f0 = make_float4(0.f, 0.f, 0.f, 0.f), f1 = f0;
            if (av) {
                f0 = *reinterpret_cast<const float4*>(&Af[elem]);
                f1 = *reinterpret_cast<const float4*>(&Af[elem + 4]);
            }
            __nv_bfloat162 h0 = __floats2bfloat162_rn(f0.x, f0.y);
            __nv_bfloat162 h1 = __floats2bfloat162_rn(f0.z, f0.w);
            __nv_bfloat162 h2 = __floats2bfloat162_rn(f1.x, f1.y);
            __nv_bfloat162 h3 = __floats2bfloat162_rn(f1.z, f1.w);
            __nv_bfloat162 l0 = __floats2bfloat162_rn(f0.x - __bfloat162float(h0.x), f0.y - __bfloat162float(h0.y));
            __nv_bfloat162 l1 = __floats2bfloat162_rn(f0.z - __bfloat162float(h1.x), f0.w - __bfloat162float(h1.y));
            __nv_bfloat162 l2 = __floats2bfloat162_rn(f1.x - __bfloat162float(h2.x), f1.y - __bfloat162float(h2.y));
            __nv_bfloat162 l3 = __floats2bfloat162_rn(f1.z - __bfloat162float(h3.x), f1.w - __bfloat162float(h3.y));
            va = make_uint4(*(uint32_t*)&h0, *(uint32_t*)&h1, *(uint32_t*)&h2, *(uint32_t*)&h3);
            vb = make_uint4(*(uint32_t*)&l0, *(uint32_t*)&l1, *(uint32_t*)&l2, *(uint32_t*)&l3);
        } else {
            va = av ? reinterpret_cast<const uint4*>(Ahi)[elem >> 3] : zero4;
            vb = av ? reinterpret_cast<const uint4*>(Alo)[elem >> 3] : zero4;
        }
        uint4 wh = reinterpret_cast<const uint4*>(Bhi)[bidx];
        uint4 wl = reinterpret_cast<const uint4*>(Blo)[bidx];
        *reinterpret_cast<uint4*>(smem + (sAhi - sb) + soff) = va;
        *reinterpret_cast<uint4*>(smem + (sAlo - sb) + soff) = vb;
        *reinterpret_cast<uint4*>(smem + (sBhi - sb) + soff) = wh;
        *reinterpret_cast<uint4*>(smem + (sBlo - sb) + soff) = wl;
    }
    __syncthreads();

#pragma unroll
    for (int kh = 0; kh < 2; kh++) {
        uint32_t hoff = (uint32_t)(kh * 16384);
#pragma unroll
        for (int kk = 0; kk < 4; kk++) {
            int lr = lane & 15;
            int kin = kk * 16 + ((lane >> 4) << 3);
            uint32_t ahi[2][4], alo[2][4], bxh[2][4], bxl[2][4];
#pragma unroll
            for (int mf = 0; mf < 2; mf++) {
                uint32_t off = hoff + SW128((uint32_t)((wm * 32 + mf * 16 + lr) * 128 + kin * 2));
                LDSM4(ahi[mf][0], ahi[mf][1], ahi[mf][2], ahi[mf][3], sAhi + off);
                LDSM4(alo[mf][0], alo[mf][1], alo[mf][2], alo[mf][3], sAlo + off);
            }
#pragma unroll
            for (int nf = 0; nf < 2; nf++) {
                uint32_t off = hoff + SW128((uint32_t)((wn * 32 + nf * 16 + lr) * 128 + kin * 2));
                LDSM4(bxh[nf][0], bxh[nf][1], bxh[nf][2], bxh[nf][3], sBhi + off);
                LDSM4(bxl[nf][0], bxl[nf][1], bxl[nf][2], bxl[nf][3], sBlo + off);
            }
#pragma unroll
            for (int mf = 0; mf < 2; mf++) {
#pragma unroll
                for (int ns = 0; ns < 4; ns++) {
                    int g = ns >> 1, od = ns & 1;
                    uint32_t bh[2] = { bxh[g][od], bxh[g][od + 2] };
                    uint32_t bl[2] = { bxl[g][od], bxl[g][od + 2] };
                    mma16816(acc[mf][ns], ahi[mf], bh);
                    mma16816(acc[mf][ns], ahi[mf], bl);
                    mma16816(acc[mf][ns], alo[mf], bh);
                }
            }
        }
    }

    int qrow = lane >> 2, qcol = (lane & 3) * 2;

    // fused alpha partial dots (fp32 accumulators)
    {
        float2 s2[4], d2[4];
#pragma unroll
        for (int ns = 0; ns < 4; ns++) {
            int c = wn * 32 + ns * 8 + qcol;
            s2[ns] = *reinterpret_cast<const float2*>(&a_src[c]);
            d2[ns] = *reinterpret_cast<const float2*>(&a_dst[c]);
        }
#pragma unroll
        for (int mf = 0; mf < 2; mf++) {
            int rl = wm * 32 + mf * 16 + qrow;
            float pa0 = 0.f, pd0 = 0.f, pa1 = 0.f, pd1 = 0.f;
#pragma unroll
            for (int ns = 0; ns < 4; ns++) {
                pa0 += acc[mf][ns][0] * s2[ns].x + acc[mf][ns][1] * s2[ns].y;
                pd0 += acc[mf][ns][0] * d2[ns].x + acc[mf][ns][1] * d2[ns].y;
                pa1 += acc[mf][ns][2] * s2[ns].x + acc[mf][ns][3] * s2[ns].y;
                pd1 += acc[mf][ns][2] * d2[ns].x + acc[mf][ns][3] * d2[ns].y;
            }
            atomicAdd(&sAl[rl][wn], pa0);     atomicAdd(&sDl[rl][wn], pd0);
            atomicAdd(&sAl[rl + 8][wn], pa1); atomicAdd(&sDl[rl + 8][wn], pd1);
        }
    }

    // h store as fp16
#pragma unroll
    for (int mf = 0; mf < 2; mf++) {
#pragma unroll
        for (int ns = 0; ns < 4; ns++) {
            int r0 = row0 + wm * 32 + mf * 16 + qrow;
            int c0 = wn * 32 + ns * 8 + qcol;
            if (r0 < n) {
                __half2 hv = __floats2half2_rn(acc[mf][ns][0], acc[mf][ns][1]);
                *reinterpret_cast<uint32_t*>(&C[(size_t)r0 * 128 + c0]) = *(uint32_t*)&hv;
            }
            if (r0 + 8 < n) {
                __half2 hv = __floats2half2_rn(acc[mf][ns][2], acc[mf][ns][3]);
                *reinterpret_cast<uint32_t*>(&C[(size_t)(r0 + 8) * 128 + c0]) = *(uint32_t*)&hv;
            }
        }
    }

    __syncthreads();
    if (tid < 128 && row0 + tid < n) {
        g_asrc[row0 + tid] = *reinterpret_cast<float4*>(&sAl[tid][0]);
        g_adst[row0 + tid] = *reinterpret_cast<float4*>(&sDl[tid][0]);
    }
}

// ---------------- dual-B HMMA GEMM (fp32 out) ----------------
#define GEMM2_SMEM 196608

__global__ void __launch_bounds__(512, 1) k_gemm_mma2(
    const __nv_bfloat16* __restrict__ Ahi, const __nv_bfloat16* __restrict__ Alo,
    const __nv_bfloat16* __restrict__ B1hi, const __nv_bfloat16* __restrict__ B1lo,
    const __nv_bfloat16* __restrict__ B2hi, const __nv_bfloat16* __restrict__ B2lo,
    float* __restrict__ C1, float* __restrict__ C2, int n)
{
    extern __shared__ char smem[];
    uint32_t sb = smem_to_u32(smem);
    const uint32_t sAhi = sb;
    const uint32_t sAlo = sb + 32768;

    int tid = threadIdx.x;
    int wid = tid >> 5, lane = tid & 31;
    int wm = wid & 3, wn = wid >> 2;
    int row0 = blockIdx.x * 128;

    const uint4 zero4 = make_uint4(0, 0, 0, 0);

#pragma unroll
    for (int t = 0; t < 4; t++) {
        int i = tid + t * 512;
        int r = i >> 4;
        int o = i & 15;
        int kh = o >> 3, oo = o & 7;
        uint32_t soff = (uint32_t)(kh * 16384) + SW128((uint32_t)(r * 128 + oo * 16));
        size_t elem = (size_t)(row0 + r) * 128 + kh * 64 + oo * 8;
        size_t bidx = ((size_t)r * 128 + kh * 64 + oo * 8) >> 3;
        bool av = (row0 + r) < n;
        uint4 va = av ? reinterpret_cast<const uint4*>(Ahi)[elem >> 3] : zero4;
        uint4 vb = av ? reinterpret_cast<const uint4*>(Alo)[elem >> 3] : zero4;
        *reinterpret_cast<uint4*>(smem + 0      + soff) = va;
        *reinterpret_cast<uint4*>(smem + 32768  + soff) = vb;
        *reinterpret_cast<uint4*>(smem + 65536  + soff) = reinterpret_cast<const uint4*>(B1hi)[bidx];
        *reinterpret_cast<uint4*>(smem + 98304  + soff) = reinterpret_cast<const uint4*>(B1lo)[bidx];
        *reinterpret_cast<uint4*>(smem + 131072 + soff) = reinterpret_cast<const uint4*>(B2hi)[bidx];
        *reinterpret_cast<uint4*>(smem + 163840 + soff) = reinterpret_cast<const uint4*>(B2lo)[bidx];
    }
    __syncthreads();

    for (int g = 0; g < 2; g++) {
        uint32_t sBhi = sb + 65536 + (uint32_t)g * 65536;
        uint32_t sBlo = sBhi + 32768;
        float* C = g ? C2 : C1;

        float acc[2][4][4];
#pragma unroll
        for (int i = 0; i < 2; i++)
#pragma unroll
            for (int j = 0; j < 4; j++)
#pragma unroll
                for (int q = 0; q < 4; q++) acc[i][j][q] = 0.f;

#pragma unroll
        for (int kh = 0; kh < 2; kh++) {
            uint32_t hoff = (uint32_t)(kh * 16384);
#pragma unroll
            for (int kk = 0; kk < 4; kk++) {
                int lr = lane & 15;
                int kin = kk * 16 + ((lane >> 4) << 3);
                uint32_t ahi[2][4], alo[2][4], bxh[2][4], bxl[2][4];
#pragma unroll
                for (int mf = 0; mf < 2; mf++) {
                    uint32_t off = hoff + SW128((uint32_t)((wm * 32 + mf * 16 + lr) * 128 + kin * 2));
                    LDSM4(ahi[mf][0], ahi[mf][1], ahi[mf][2], ahi[mf][3], sAhi + off);
                    LDSM4(alo[mf][0], alo[mf][1], alo[mf][2], alo[mf][3], sAlo + off);
                }
#pragma unroll
                for (int nf = 0; nf < 2; nf++) {
                    uint32_t off = hoff + SW128((uint32_t)((wn * 32 + nf * 16 + lr) * 128 + kin * 2));
                    LDSM4(bxh[nf][0], bxh[nf][1], bxh[nf][2], bxh[nf][3], sBhi + off);
                    LDSM4(bxl[nf][0], bxl[nf][1], bxl[nf][2], bxl[nf][3], sBlo + off);
                }
#pragma unroll
                for (int mf = 0; mf < 2; mf++) {
#pragma unroll
                    for (int ns = 0; ns < 4; ns++) {
                        int gg = ns >> 1, od = ns & 1;
                        uint32_t bh[2] = { bxh[gg][od], bxh[gg][od + 2] };
                        uint32_t bl[2] = { bxl[gg][od], bxl[gg][od + 2] };
                        mma16816(acc[mf][ns], ahi[mf], bh);
                        mma16816(acc[mf][ns], ahi[mf], bl);
                        mma16816(acc[mf][ns], alo[mf], bh);
                    }
                }
            }
        }

        int qrow = lane >> 2, qcol = (lane & 3) * 2;
#pragma unroll
        for (int mf = 0; mf < 2; mf++) {
#pragma unroll
            for (int ns = 0; ns < 4; ns++) {
                int r0 = row0 + wm * 32 + mf * 16 + qrow;
                int c0 = wn * 32 + ns * 8 + qcol;
                if (r0 < n)
                    *reinterpret_cast<float2*>(&C[(size_t)r0 * 128 + c0]) =
                        make_float2(acc[mf][ns][0], acc[mf][ns][1]);
                if (r0 + 8 < n)
                    *reinterpret_cast<float2*>(&C[(size_t)(r0 + 8) * 128 + c0]) =
                        make_float2(acc[mf][ns][2], acc[mf][ns][3]);
            }
        }
    }
}

// ---------------- warp helpers ----------------
__device__ __forceinline__ float warp_sum(float v) {
#pragma unroll
    for (int o = 16; o; o >>= 1) v += __shfl_xor_sync(0xffffffffu, v, o);
    return v;
}

__device__ __forceinline__ float lrelu(float x) { return x >= 0.f ? x : 0.2f * x; }
__device__ __forceinline__ float elu(float x)  { return x > 0.f ? x : expm1f(x); }

// ---------------- fused GAT aggregation (fp16 h gather) ----------------
__global__ void k_edgeagg(const __half* __restrict__ h,
                          const float* __restrict__ xprev,
                          float* __restrict__ xnext,
                          __nv_bfloat16* __restrict__ hi,
                          __nv_bfloat16* __restrict__ lo, int n)
{
    __shared__ int   sidx[8][32];
    __shared__ float4 swt[8][32];

    int w = threadIdx.x >> 5;
    int gw = (blockIdx.x * blockDim.x + threadIdx.x) >> 5;
    int lane = threadIdx.x & 31;
    if (gw >= n) return;

    int base = g_rowptr[gw];
    int deg  = g_rowptr[gw + 1] - base;
    float4 ad = g_adst[gw];
    float4 acc = make_float4(0.f, 0.f, 0.f, 0.f);
    int hsel = lane >> 3;

    if (deg <= 32) {
        // fast path: single 32-edge block, no g_ew round-trip
        int myidx = 0;
        float p0 = 0.f, p1 = 0.f, p2 = 0.f, p3 = 0.f;
        if (lane < deg) {
            myidx = g_col[base + lane];
            float4 as = g_asrc[myidx];
            p0 = expf(fminf(lrelu(as.x + ad.x), 75.f));
            p1 = expf(fminf(lrelu(as.y + ad.y), 75.f));
            p2 = expf(fminf(lrelu(as.z + ad.z), 75.f));
            p3 = expf(fminf(lrelu(as.w + ad.w), 75.f));
        }
        float i0 = 1.f / (warp_sum(p0) + 1e-10f);
        float i1 = 1.f / (warp_sum(p1) + 1e-10f);
        float i2 = 1.f / (warp_sum(p2) + 1e-10f);
        float i3 = 1.f / (warp_sum(p3) + 1e-10f);
        sidx[w][lane] = myidx;
        swt[w][lane] = make_float4(p0 * i0, p1 * i1, p2 * i2, p3 * i3);
        __syncwarp();
#pragma unroll 4
        for (int j = 0; j < deg; j++) {
            int s = sidx[w][j];
            float wj = reinterpret_cast<const float*>(&swt[w][j])[hsel];
            uint2 raw = *reinterpret_cast<const uint2*>(&h[(size_t)s * 128 + 4 * lane]);
            float2 f01 = __half22float2(*reinterpret_cast<const __half2*>(&raw.x));
            float2 f23 = __half22float2(*reinterpret_cast<const __half2*>(&raw.y));
            acc.x += f01.x * wj;
            acc.y += f01.y * wj;
            acc.z += f23.x * wj;
            acc.w += f23.y * wj;
        }
    } else {
        // general path
        float s0 = 0.f, s1 = 0.f, s2 = 0.f, s3 = 0.f;
        for (int i = lane; i < deg; i += 32) {
            int s = g_col[base + i];
            float4 as = g_asrc[s];
            float p0 = expf(fminf(lrelu(as.x + ad.x), 75.f));
            float p1 = expf(fminf(lrelu(as.y + ad.y), 75.f));
            float p2 = expf(fminf(lrelu(as.z + ad.z), 75.f));
            float p3 = expf(fminf(lrelu(as.w + ad.w), 75.f));
            g_ew[base + i] = make_float4(p0, p1, p2, p3);
            s0 += p0; s1 += p1; s2 += p2; s3 += p3;
        }
        s0 = warp_sum(s0); s1 = warp_sum(s1); s2 = warp_sum(s2); s3 = warp_sum(s3);
        float i0 = 1.f / (s0 + 1e-10f);
        float i1 = 1.f / (s1 + 1e-10f);
        float i2 = 1.f / (s2 + 1e-10f);
        float i3 = 1.f / (s3 + 1e-10f);

        for (int bi = 0; bi < deg; bi += 32) {
            int cnt = min(32, deg - bi);
            if (lane < cnt) {
                sidx[w][lane] = g_col[base + bi + lane];
                float4 p = g_ew[base + bi + lane];
                swt[w][lane] = make_float4(p.x * i0, p.y * i1, p.z * i2, p.w * i3);
            }
            __syncwarp();
#pragma unroll 4
            for (int j = 0; j < cnt; j++) {
                int s = sidx[w][j];
                float wj = reinterpret_cast<const float*>(&swt[w][j])[hsel];
                uint2 raw = *reinterpret_cast<const uint2*>(&h[(size_t)s * 128 + 4 * lane]);
                float2 f01 = __half22float2(*reinterpret_cast<const __half2*>(&raw.x));
                float2 f23 = __half22float2(*reinterpret_cast<const __half2*>(&raw.y));
                acc.x += f01.x * wj;
                acc.y += f01.y * wj;
                acc.z += f23.x * wj;
                acc.w += f23.y * wj;
            }
            __syncwarp();
        }
    }

    size_t o = (size_t)gw * 128 + 4 * lane;
    float4 xp = *reinterpret_cast<const float4*>(&xprev[o]);
    float4 v = make_float4(elu(acc.x) + xp.x, elu(acc.y) + xp.y,
                           elu(acc.z) + xp.z, elu(acc.w) + xp.w);
    if (xnext) *reinterpret_cast<float4*>(&xnext[o]) = v;
    if (hi) {
        __nv_bfloat162 h0 = __floats2bfloat162_rn(v.x, v.y);
        __nv_bfloat162 h1 = __floats2bfloat162_rn(v.z, v.w);
        __nv_bfloat162 l0 = __floats2bfloat162_rn(v.x - __bfloat162float(h0.x), v.y - __bfloat162float(h0.y));
        __nv_bfloat162 l1 = __floats2bfloat162_rn(v.z - __bfloat162float(h1.x), v.w - __bfloat162float(h1.y));
        uint2 ph = make_uint2(*(uint32_t*)&h0, *(uint32_t*)&h1);
        uint2 pl = make_uint2(*(uint32_t*)&l0, *(uint32_t*)&l1);
        *reinterpret_cast<uint2*>(&hi[o]) = ph;
        *reinterpret_cast<uint2*>(&lo[o]) = pl;
    }
}

// ---------------- pair epilogue ----------------
__global__ void k_pairs(const int* __restrict__ lsrc, const int* __restrict__ ldst,
                        const float* __restrict__ b1, const float* __restrict__ w2,
                        const float* __restrict__ b2, float* __restrict__ out, int p)
{
    int gw = (blockIdx.x * blockDim.x + threadIdx.x) >> 5;
    int lane = threadIdx.x & 31;
    if (gw >= p) return;
    int k = 4 * lane;
    float4 u = *reinterpret_cast<const float4*>(&g_u[(size_t)lsrc[gw] * 128 + k]);
    float4 v = *reinterpret_cast<const float4*>(&g_v[(size_t)ldst[gw] * 128 + k]);
    float4 b = *reinterpret_cast<const float4*>(&b1[k]);
    float4 w = *reinterpret_cast<const float4*>(&w2[k]);
    float t = fmaxf(u.x + v.x + b.x, 0.f) * w.x
            + fmaxf(u.y + v.y + b.y, 0.f) * w.y
            + fmaxf(u.z + v.z + b.z, 0.f) * w.z
            + fmaxf(u.w + v.w + b.w, 0.f) * w.w;
    t = warp_sum(t);
    if (lane == 0) out[gw] = t + b2[0];
}

// ---------------- driver (serial, single stream) ----------------
extern "C" void kernel_launch(void* const* d_in, const int* in_sizes, int n_in,
                              void* d_out, int out_size)
{
    const float* embed  = (const float*)d_in[0];
    const float* W1     = (const float*)d_in[1];
    const float* a_src1 = (const float*)d_in[2];
    const float* a_dst1 = (const float*)d_in[3];
    const float* W2     = (const float*)d_in[4];
    const float* a_src2 = (const float*)d_in[5];
    const float* a_dst2 = (const float*)d_in[6];
    const float* lp_w1  = (const float*)d_in[7];
    const float* lp_b1  = (const float*)d_in[8];
    const float* lp_w2  = (const float*)d_in[9];
    const float* lp_b2  = (const float*)d_in[10];
    const int*   eidx   = (const int*)d_in[11];
    const int*   lsrc   = (const int*)d_in[12];
    const int*   ldst   = (const int*)d_in[13];
    float* out = (float*)d_out;

    const int N = in_sizes[0] / DDIM;
    const int E = in_sizes[11] / 2;
    const int P = in_sizes[12];
    const int* esrc = eidx;
    const int* edst = eidx + E;

    __half* hbuf; cudaGetSymbolAddress((void**)&hbuf, g_h);
    float* x2;   cudaGetSymbolAddress((void**)&x2,   g_x2);
    float* ub;   cudaGetSymbolAddress((void**)&ub,   g_u);
    float* vb;   cudaGetSymbolAddress((void**)&vb,   g_v);
    __nv_bfloat16* ahi; cudaGetSymbolAddress((void**)&ahi, g_ahi);
    __nv_bfloat16* alo; cudaGetSymbolAddress((void**)&alo, g_alo);
    __nv_bfloat16* wthi; cudaGetSymbolAddress((void**)&wthi, g_wthi);
    __nv_bfloat16* wtlo; cudaGetSymbolAddress((void**)&wtlo, g_wtlo);

    cudaFuncSetAttribute(k_gemm_mma,  cudaFuncAttributeMaxDynamicSharedMemorySize, GEMM_SMEM);
    cudaFuncSetAttribute(k_gemm_mma2, cudaFuncAttributeMaxDynamicSharedMemorySize, GEMM2_SMEM);

    const int T = 256;
    int nbN  = (N + T - 1) / T;
    int nbE  = (E + T - 1) / T;
    int nbS  = (N + 1023) / 1024;
    int nbW  = (N * 32 + T - 1) / T;
    int nbPW = (P * 32 + T - 1) / T;
    int nbG  = (N + 127) / 128;
    const int WSZ = DDIM * DDIM;

    // setup + CSR
    k_setup<<<nbN, T>>>(W1, W2, lp_w1, wthi, wtlo, N);
    k_hist<<<nbE, T>>>(edst, E);
    k_scan1<<<nbS, 1024>>>(N);
    k_scan2<<<1, 128>>>(nbS);
    k_scan3<<<nbS, 1024>>>(N, E);
    k_scatter<<<nbE, T>>>(esrc, edst, E);

    // layer 1
    k_gemm_mma<<<nbG, 512, GEMM_SMEM>>>(embed, nullptr, nullptr,
                                        wthi + 0 * WSZ, wtlo + 0 * WSZ, hbuf,
                                        a_src1, a_dst1, N);
    k_edgeagg<<<nbW, T>>>(hbuf, embed, x2, ahi, alo, N);

    // layer 2
    k_gemm_mma<<<nbG, 512, GEMM_SMEM>>>(nullptr, ahi, alo,
                                        wthi + 1 * WSZ, wtlo + 1 * WSZ, hbuf,
                                        a_src2, a_dst2, N);
    k_edgeagg<<<nbW, T>>>(hbuf, x2, nullptr, ahi, alo, N);

    // link predictor
    k_gemm_mma2<<<nbG, 512, GEMM2_SMEM>>>(ahi, alo,
                                          wthi + 2 * WSZ, wtlo + 2 * WSZ,
                                          wthi + 3 * WSZ, wtlo + 3 * WSZ,
                                          ub, vb, N);
    k_pairs<<<nbPW, T>>>(lsrc, ldst, lp_b1, lp_w2, lp_b2, out, P);
}

// round 10
// speedup vs baseline: 1.0939x; 1.0156x over previous
#include <cuda_runtime.h>
#include <cuda_bf16.h>
#include <cuda_fp16.h>
#include <math.h>
#include <stdint.h>

#define NMAX 100000
#define EMAX 1600000
#define DDIM 128

// ---------------- scratch ----------------
__device__ __half g_h [NMAX * DDIM];          // fp16 transformed features
__device__ __half g_u [NMAX * DDIM];          // fp16 link-pred partials
__device__ __half g_v [NMAX * DDIM];
__device__ __nv_bfloat16 g_ahi[NMAX * DDIM];  // bf16 hi/lo of current x
__device__ __nv_bfloat16 g_alo[NMAX * DDIM];
__device__ __nv_bfloat16 g_wthi[4 * DDIM * DDIM];
__device__ __nv_bfloat16 g_wtlo[4 * DDIM * DDIM];
__device__ float4 g_asrc[NMAX];
__device__ float4 g_adst[NMAX];
__device__ float4 g_ew  [EMAX];
__device__ int g_deg   [NMAX];
__device__ int g_rowptr[NMAX + 1];
__device__ int g_cursor[NMAX];
__device__ int g_col   [EMAX];
__device__ int g_bsums [1024];

__device__ __forceinline__ uint32_t smem_to_u32(const void* p) {
    uint32_t a;
    asm("{ .reg .u64 t; cvta.to.shared.u64 t, %1; cvt.u32.u64 %0, t; }" : "=r"(a) : "l"(p));
    return a;
}
#define SW128(off) ((off) ^ (((off) >> 3) & 0x70))

#define LDSM4(r0, r1, r2, r3, addr) \
    asm volatile("ldmatrix.sync.aligned.m8n8.x4.shared.b16 {%0,%1,%2,%3}, [%4];" \
        : "=r"(r0), "=r"(r1), "=r"(r2), "=r"(r3) : "r"(addr))

__device__ __forceinline__ void mma16816(float* d, const uint32_t* a, const uint32_t* b) {
    asm volatile(
        "mma.sync.aligned.m16n8k16.row.col.f32.bf16.bf16.f32 "
        "{%0,%1,%2,%3},{%4,%5,%6,%7},{%8,%9},{%0,%1,%2,%3};"
        : "+f"(d[0]), "+f"(d[1]), "+f"(d[2]), "+f"(d[3])
        : "r"(a[0]), "r"(a[1]), "r"(a[2]), "r"(a[3]), "r"(b[0]), "r"(b[1]));
}

// ---------------- setup: zero degrees + all 4 weight splits ----------------
__device__ __forceinline__ void wsplit_one(const float* __restrict__ W,
                                           __nv_bfloat16* __restrict__ hi,
                                           __nv_bfloat16* __restrict__ lo, int i) {
    int nn = i >> 6;
    int kp = (i & 63) * 2;
    float x0 = W[(size_t)kp * 128 + nn];
    float x1 = W[(size_t)(kp + 1) * 128 + nn];
    __nv_bfloat162 h = __floats2bfloat162_rn(x0, x1);
    float r0 = x0 - __bfloat162float(h.x);
    float r1 = x1 - __bfloat162float(h.y);
    __nv_bfloat162 l = __floats2bfloat162_rn(r0, r1);
    reinterpret_cast<__nv_bfloat162*>(hi)[i] = h;
    reinterpret_cast<__nv_bfloat162*>(lo)[i] = l;
}

__global__ void k_setup(const float* __restrict__ W1, const float* __restrict__ W2,
                        const float* __restrict__ lpw1,
                        __nv_bfloat16* __restrict__ wthi, __nv_bfloat16* __restrict__ wtlo,
                        int n) {
    const int WSZ = DDIM * DDIM;
    int i = blockIdx.x * blockDim.x + threadIdx.x;
    if (i < n) g_deg[i] = 0;
    if (i < 8192)       wsplit_one(W1,               wthi + 0 * WSZ, wtlo + 0 * WSZ, i);
    else if (i < 16384) wsplit_one(W2,               wthi + 1 * WSZ, wtlo + 1 * WSZ, i - 8192);
    else if (i < 24576) wsplit_one(lpw1,             wthi + 2 * WSZ, wtlo + 2 * WSZ, i - 16384);
    else if (i < 32768) wsplit_one(lpw1 + 128 * 128, wthi + 3 * WSZ, wtlo + 3 * WSZ, i - 24576);
}

// ---------------- CSR build ----------------
__global__ void k_hist(const int* __restrict__ dst, int e) {
    int i = blockIdx.x * blockDim.x + threadIdx.x;
    if (i < e) atomicAdd(&g_deg[dst[i]], 1);
}
__global__ void k_scan1(int n) {
    __shared__ int ws[32];
    int tid = threadIdx.x;
    int lane = tid & 31, w = tid >> 5;
    int i = blockIdx.x * 1024 + tid;
    int v = (i < n) ? g_deg[i] : 0;
    int x = v;
#pragma unroll
    for (int o = 1; o < 32; o <<= 1) {
        int t = __shfl_up_sync(0xffffffffu, x, o);
        if (lane >= o) x += t;
    }
    if (lane == 31) ws[w] = x;
    __syncthreads();
    if (w == 0) {
        int t = ws[lane];
        int s = t;
#pragma unroll
        for (int o = 1; o < 32; o <<= 1) {
            int q = __shfl_up_sync(0xffffffffu, s, o);
            if (lane >= o) s += q;
        }
        ws[lane] = s - t;   // exclusive warp offsets
    }
    __syncthreads();
    int incl = x + ws[w];
    if (i < n) g_rowptr[i] = incl - v;
    if (tid == 1023) g_bsums[blockIdx.x] = incl;
}
__global__ void k_scan2(int nb) {       // nb <= 128
    __shared__ int wsum[4];
    int tid = threadIdx.x;
    int lane = tid & 31, w = tid >> 5;
    int v = (tid < nb) ? g_bsums[tid] : 0;
    int x = v;
#pragma unroll
    for (int o = 1; o < 32; o <<= 1) {
        int t = __shfl_up_sync(0xffffffffu, x, o);
        if (lane >= o) x += t;
    }
    if (lane == 31) wsum[w] = x;
    __syncthreads();
    int add = 0;
#pragma unroll
    for (int j = 0; j < 4; j++) add += (j < w) ? wsum[j] : 0;
    if (tid < nb) g_bsums[tid] = x - v + add;
}
__global__ void k_scan3(int n, int e) {
    int i = blockIdx.x * 1024 + threadIdx.x;
    if (i < n) {
        int v = g_rowptr[i] + g_bsums[blockIdx.x];
        g_rowptr[i] = v;
        g_cursor[i] = v;
    }
    if (i == 0) g_rowptr[n] = e;
}
__global__ void k_scatter(const int* __restrict__ src, const int* __restrict__ dst, int e) {
    int i = blockIdx.x * blockDim.x + threadIdx.x;
    if (i < e) {
        int d = dst[i];
        int slot = atomicAdd(&g_cursor[d], 1);
        g_col[slot] = src[i];
    }
}

// ---------------- HMMA GEMM + fused alpha, fp16 h output ----------------
#define GEMM_SMEM 131072

__global__ void __launch_bounds__(512, 1) k_gemm_mma(
    const float* __restrict__ Af,
    const __nv_bfloat16* __restrict__ Ahi, const __nv_bfloat16* __restrict__ Alo,
    const __nv_bfloat16* __restrict__ Bhi, const __nv_bfloat16* __restrict__ Blo,
    __half* __restrict__ C,
    const float* __restrict__ a_src, const float* __restrict__ a_dst, int n)
{
    extern __shared__ char smem[];
    __shared__ float sAl[128][4];
    __shared__ float sDl[128][4];
    uint32_t sb = smem_to_u32(smem);
    const uint32_t sAhi = sb;
    const uint32_t sAlo = sb + 32768;
    const uint32_t sBhi = sb + 65536;
    const uint32_t sBlo = sb + 98304;

    int tid = threadIdx.x;
    int wid = tid >> 5, lane = tid & 31;
    int wm = wid & 3, wn = wid >> 2;
    int row0 = blockIdx.x * 128;

    if (tid < 128) {
        *reinterpret_cast<float4*>(&sAl[tid][0]) = make_float4(0.f, 0.f, 0.f, 0.f);
        *reinterpret_cast<float4*>(&sDl[tid][0]) = make_float4(0.f, 0.f, 0.f, 0.f);
    }

    float acc[2][4][4];
#pragma unroll
    for (int i = 0; i < 2; i++)
#pragma unroll
        for (int j = 0; j < 4; j++)
#pragma unroll
            for (int q = 0; q < 4; q++) acc[i][j][q] = 0.f;

    const uint4 zero4 = make_uint4(0, 0, 0, 0);

#pragma unroll
    for (int t = 0; t < 4; t++) {
        int i = tid + t * 512;
        int r = i >> 4;
        int o = i & 15;
        int kh = o >> 3, oo = o & 7;
        uint32_t soff = (uint32_t)(kh * 16384) + SW128((uint32_t)(r * 128 + oo * 16));
        size_t elem = (size_t)(row0 + r) * 128 + kh * 64 + oo * 8;
        size_t bidx = ((size_t)r * 128 + kh * 64 + oo * 8) >> 3;
        bool av = (row0 + r) < n;
        uint4 va, vb;
        if (Af) {
            float4 f0 = make_float4(0.f, 0.f, 0.f, 0.f), f1 = f0;
            if (av) {
                f0 = *reinterpret_cast<const float4*>(&Af[elem]);
                f1 = *reinterpret_cast<const float4*>(&Af[elem + 4]);
            }
            __nv_bfloat162 h0 = __floats2bfloat162_rn(f0.x, f0.y);
            __nv_bfloat162 h1 = __floats2bfloat162_rn(f0.z, f0.w);
            __nv_bfloat162 h2 = __floats2bfloat162_rn(f1.x, f1.y);
            __nv_bfloat162 h3 = __floats2bfloat162_rn(f1.z, f1.w);
            __nv_bfloat162 l0 = __floats2bfloat162_rn(f0.x - __bfloat162float(h0.x), f0.y - __bfloat162float(h0.y));
            __nv_bfloat162 l1 = __floats2bfloat162_rn(f0.z - __bfloat162float(h1.x), f0.w - __bfloat162float(h1.y));
            __nv_bfloat162 l2 = __floats2bfloat162_rn(f1.x - __bfloat162float(h2.x), f1.y - __bfloat162float(h2.y));
            __nv_bfloat162 l3 = __floats2bfloat162_rn(f1.z - __bfloat162float(h3.x), f1.w - __bfloat162float(h3.y));
            va = make_uint4(*(uint32_t*)&h0, *(uint32_t*)&h1, *(uint32_t*)&h2, *(uint32_t*)&h3);
            vb = make_uint4(*(uint32_t*)&l0, *(uint32_t*)&l1, *(uint32_t*)&l2, *(uint32_t*)&l3);
        } else {
            va = av ? reinterpret_cast<const uint4*>(Ahi)[elem >> 3] : zero4;
            vb = av ? reinterpret_cast<const uint4*>(Alo)[elem >> 3] : zero4;
        }
        uint4 wh = reinterpret_cast<const uint4*>(Bhi)[bidx];
        uint4 wl = reinterpret_cast<const uint4*>(Blo)[bidx];
        *reinterpret_cast<uint4*>(smem + (sAhi - sb) + soff) = va;
        *reinterpret_cast<uint4*>(smem + (sAlo - sb) + soff) = vb;
        *reinterpret_cast<uint4*>(smem + (sBhi - sb) + soff) = wh;
        *reinterpret_cast<uint4*>(smem + (sBlo - sb) + soff) = wl;
    }
    __syncthreads();

#pragma unroll
    for (int kh = 0; kh < 2; kh++) {
        uint32_t hoff = (uint32_t)(kh * 16384);
#pragma unroll
        for (int kk = 0; kk < 4; kk++) {
            int lr = lane & 15;
            int kin = kk * 16 + ((lane >> 4) << 3);
            uint32_t ahi[2][4], alo[2][4], bxh[2][4], bxl[2][4];
#pragma unroll
            for (int mf = 0; mf < 2; mf++) {
                uint32_t off = hoff + SW128((uint32_t)((wm * 32 + mf * 16 + lr) * 128 + kin * 2));
                LDSM4(ahi[mf][0], ahi[mf][1], ahi[mf][2], ahi[mf][3], sAhi + off);
                LDSM4(alo[mf][0], alo[mf][1], alo[mf][2], alo[mf][3], sAlo + off);
            }
#pragma unroll
            for (int nf = 0; nf < 2; nf++) {
                uint32_t off = hoff + SW128((uint32_t)((wn * 32 + nf * 16 + lr) * 128 + kin * 2));
                LDSM4(bxh[nf][0], bxh[nf][1], bxh[nf][2], bxh[nf][3], sBhi + off);
                LDSM4(bxl[nf][0], bxl[nf][1], bxl[nf][2], bxl[nf][3], sBlo + off);
            }
#pragma unroll
            for (int mf = 0; mf < 2; mf++) {
#pragma unroll
                for (int ns = 0; ns < 4; ns++) {
                    int g = ns >> 1, od = ns & 1;
                    uint32_t bh[2] = { bxh[g][od], bxh[g][od + 2] };
                    uint32_t bl[2] = { bxl[g][od], bxl[g][od + 2] };
                    mma16816(acc[mf][ns], ahi[mf], bh);
                    mma16816(acc[mf][ns], ahi[mf], bl);
                    mma16816(acc[mf][ns], alo[mf], bh);
                }
            }
        }
    }

    int qrow = lane >> 2, qcol = (lane & 3) * 2;

    // fused alpha partial dots (fp32 accumulators)
    {
        float2 s2[4], d2[4];
#pragma unroll
        for (int ns = 0; ns < 4; ns++) {
            int c = wn * 32 + ns * 8 + qcol;
            s2[ns] = *reinterpret_cast<const float2*>(&a_src[c]);
            d2[ns] = *reinterpret_cast<const float2*>(&a_dst[c]);
        }
#pragma unroll
        for (int mf = 0; mf < 2; mf++) {
            int rl = wm * 32 + mf * 16 + qrow;
            float pa0 = 0.f, pd0 = 0.f, pa1 = 0.f, pd1 = 0.f;
#pragma unroll
            for (int ns = 0; ns < 4; ns++) {
                pa0 += acc[mf][ns][0] * s2[ns].x + acc[mf][ns][1] * s2[ns].y;
                pd0 += acc[mf][ns][0] * d2[ns].x + acc[mf][ns][1] * d2[ns].y;
                pa1 += acc[mf][ns][2] * s2[ns].x + acc[mf][ns][3] * s2[ns].y;
                pd1 += acc[mf][ns][2] * d2[ns].x + acc[mf][ns][3] * d2[ns].y;
            }
            atomicAdd(&sAl[rl][wn], pa0);     atomicAdd(&sDl[rl][wn], pd0);
            atomicAdd(&sAl[rl + 8][wn], pa1); atomicAdd(&sDl[rl + 8][wn], pd1);
        }
    }

    // h store as fp16
#pragma unroll
    for (int mf = 0; mf < 2; mf++) {
#pragma unroll
        for (int ns = 0; ns < 4; ns++) {
            int r0 = row0 + wm * 32 + mf * 16 + qrow;
            int c0 = wn * 32 + ns * 8 + qcol;
            if (r0 < n) {
                __half2 hv = __floats2half2_rn(acc[mf][ns][0], acc[mf][ns][1]);
                *reinterpret_cast<uint32_t*>(&C[(size_t)r0 * 128 + c0]) = *(uint32_t*)&hv;
            }
            if (r0 + 8 < n) {
                __half2 hv = __floats2half2_rn(acc[mf][ns][2], acc[mf][ns][3]);
                *reinterpret_cast<uint32_t*>(&C[(size_t)(r0 + 8) * 128 + c0]) = *(uint32_t*)&hv;
            }
        }
    }

    __syncthreads();
    if (tid < 128 && row0 + tid < n) {
        g_asrc[row0 + tid] = *reinterpret_cast<float4*>(&sAl[tid][0]);
        g_adst[row0 + tid] = *reinterpret_cast<float4*>(&sDl[tid][0]);
    }
}

// ---------------- dual-B HMMA GEMM (fp16 out) ----------------
#define GEMM2_SMEM 196608

__global__ void __launch_bounds__(512, 1) k_gemm_mma2(
    const __nv_bfloat16* __restrict__ Ahi, const __nv_bfloat16* __restrict__ Alo,
    const __nv_bfloat16* __restrict__ B1hi, const __nv_bfloat16* __restrict__ B1lo,
    const __nv_bfloat16* __restrict__ B2hi, const __nv_bfloat16* __restrict__ B2lo,
    __half* __restrict__ C1, __half* __restrict__ C2, int n)
{
    extern __shared__ char smem[];
    uint32_t sb = smem_to_u32(smem);
    const uint32_t sAhi = sb;
    const uint32_t sAlo = sb + 32768;

    int tid = threadIdx.x;
    int wid = tid >> 5, lane = tid & 31;
    int wm = wid & 3, wn = wid >> 2;
    int row0 = blockIdx.x * 128;

    const uint4 zero4 = make_uint4(0, 0, 0, 0);

#pragma unroll
    for (int t = 0; t < 4; t++) {
        int i = tid + t * 512;
        int r = i >> 4;
        int o = i & 15;
        int kh = o >> 3, oo = o & 7;
        uint32_t soff = (uint32_t)(kh * 16384) + SW128((uint32_t)(r * 128 + oo * 16));
        size_t elem = (size_t)(row0 + r) * 128 + kh * 64 + oo * 8;
        size_t bidx = ((size_t)r * 128 + kh * 64 + oo * 8) >> 3;
        bool av = (row0 + r) < n;
        uint4 va = av ? reinterpret_cast<const uint4*>(Ahi)[elem >> 3] : zero4;
        uint4 vb = av ? reinterpret_cast<const uint4*>(Alo)[elem >> 3] : zero4;
        *reinterpret_cast<uint4*>(smem + 0      + soff) = va;
        *reinterpret_cast<uint4*>(smem + 32768  + soff) = vb;
        *reinterpret_cast<uint4*>(smem + 65536  + soff) = reinterpret_cast<const uint4*>(B1hi)[bidx];
        *reinterpret_cast<uint4*>(smem + 98304  + soff) = reinterpret_cast<const uint4*>(B1lo)[bidx];
        *reinterpret_cast<uint4*>(smem + 131072 + soff) = reinterpret_cast<const uint4*>(B2hi)[bidx];
        *reinterpret_cast<uint4*>(smem + 163840 + soff) = reinterpret_cast<const uint4*>(B2lo)[bidx];
    }
    __syncthreads();

    for (int g = 0; g < 2; g++) {
        uint32_t sBhi = sb + 65536 + (uint32_t)g * 65536;
        uint32_t sBlo = sBhi + 32768;
        __half* C = g ? C2 : C1;

        float acc[2][4][4];
#pragma unroll
        for (int i = 0; i < 2; i++)
#pragma unroll
            for (int j = 0; j < 4; j++)
#pragma unroll
                for (int q = 0; q < 4; q++) acc[i][j][q] = 0.f;

#pragma unroll
        for (int kh = 0; kh < 2; kh++) {
            uint32_t hoff = (uint32_t)(kh * 16384);
#pragma unroll
            for (int kk = 0; kk < 4; kk++) {
                int lr = lane & 15;
                int kin = kk * 16 + ((lane >> 4) << 3);
                uint32_t ahi[2][4], alo[2][4], bxh[2][4], bxl[2][4];
#pragma unroll
                for (int mf = 0; mf < 2; mf++) {
                    uint32_t off = hoff + SW128((uint32_t)((wm * 32 + mf * 16 + lr) * 128 + kin * 2));
                    LDSM4(ahi[mf][0], ahi[mf][1], ahi[mf][2], ahi[mf][3], sAhi + off);
                    LDSM4(alo[mf][0], alo[mf][1], alo[mf][2], alo[mf][3], sAlo + off);
                }
#pragma unroll
                for (int nf = 0; nf < 2; nf++) {
                    uint32_t off = hoff + SW128((uint32_t)((wn * 32 + nf * 16 + lr) * 128 + kin * 2));
                    LDSM4(bxh[nf][0], bxh[nf][1], bxh[nf][2], bxh[nf][3], sBhi + off);
                    LDSM4(bxl[nf][0], bxl[nf][1], bxl[nf][2], bxl[nf][3], sBlo + off);
                }
#pragma unroll
                for (int mf = 0; mf < 2; mf++) {
#pragma unroll
                    for (int ns = 0; ns < 4; ns++) {
                        int gg = ns >> 1, od = ns & 1;
                        uint32_t bh[2] = { bxh[gg][od], bxh[gg][od + 2] };
                        uint32_t bl[2] = { bxl[gg][od], bxl[gg][od + 2] };
                        mma16816(acc[mf][ns], ahi[mf], bh);
                        mma16816(acc[mf][ns], ahi[mf], bl);
                        mma16816(acc[mf][ns], alo[mf], bh);
                    }
                }
            }
        }

        int qrow = lane >> 2, qcol = (lane & 3) * 2;
#pragma unroll
        for (int mf = 0; mf < 2; mf++) {
#pragma unroll
            for (int ns = 0; ns < 4; ns++) {
                int r0 = row0 + wm * 32 + mf * 16 + qrow;
                int c0 = wn * 32 + ns * 8 + qcol;
                if (r0 < n) {
                    __half2 hv = __floats2half2_rn(acc[mf][ns][0], acc[mf][ns][1]);
                    *reinterpret_cast<uint32_t*>(&C[(size_t)r0 * 128 + c0]) = *(uint32_t*)&hv;
                }
                if (r0 + 8 < n) {
                    __half2 hv = __floats2half2_rn(acc[mf][ns][2], acc[mf][ns][3]);
                    *reinterpret_cast<uint32_t*>(&C[(size_t)(r0 + 8) * 128 + c0]) = *(uint32_t*)&hv;
                }
            }
        }
    }
}

// ---------------- warp helpers ----------------
__device__ __forceinline__ float warp_sum(float v) {
#pragma unroll
    for (int o = 16; o; o >>= 1) v += __shfl_xor_sync(0xffffffffu, v, o);
    return v;
}

__device__ __forceinline__ float lrelu(float x) { return x >= 0.f ? x : 0.2f * x; }
__device__ __forceinline__ float elu(float x)  { return x > 0.f ? x : expm1f(x); }

// ---------------- fused GAT aggregation ----------------
// xprev: fp32 if xprev_f != null, else reconstructed from xhi+xlo (in place).
// Output always written to xhi/xlo (bf16 split).
__global__ void k_edgeagg(const __half* __restrict__ h,
                          const float* __restrict__ xprev_f,
                          __nv_bfloat16* __restrict__ xhi,
                          __nv_bfloat16* __restrict__ xlo, int n)
{
    __shared__ int   sidx[8][32];
    __shared__ float4 swt[8][32];

    int w = threadIdx.x >> 5;
    int gw = (blockIdx.x * blockDim.x + threadIdx.x) >> 5;
    int lane = threadIdx.x & 31;
    if (gw >= n) return;

    int base = g_rowptr[gw];
    int deg  = g_rowptr[gw + 1] - base;
    float4 ad = g_adst[gw];
    float4 acc = make_float4(0.f, 0.f, 0.f, 0.f);
    int hsel = lane >> 3;

    if (deg <= 32) {
        int myidx = 0;
        float p0 = 0.f, p1 = 0.f, p2 = 0.f, p3 = 0.f;
        if (lane < deg) {
            myidx = g_col[base + lane];
            float4 as = g_asrc[myidx];
            p0 = expf(fminf(lrelu(as.x + ad.x), 75.f));
            p1 = expf(fminf(lrelu(as.y + ad.y), 75.f));
            p2 = expf(fminf(lrelu(as.z + ad.z), 75.f));
            p3 = expf(fminf(lrelu(as.w + ad.w), 75.f));
        }
        float i0 = 1.f / (warp_sum(p0) + 1e-10f);
        float i1 = 1.f / (warp_sum(p1) + 1e-10f);
        float i2 = 1.f / (warp_sum(p2) + 1e-10f);
        float i3 = 1.f / (warp_sum(p3) + 1e-10f);
        sidx[w][lane] = myidx;
        swt[w][lane] = make_float4(p0 * i0, p1 * i1, p2 * i2, p3 * i3);
        __syncwarp();
#pragma unroll 4
        for (int j = 0; j < deg; j++) {
            int s = sidx[w][j];
            float wj = reinterpret_cast<const float*>(&swt[w][j])[hsel];
            uint2 raw = *reinterpret_cast<const uint2*>(&h[(size_t)s * 128 + 4 * lane]);
            float2 f01 = __half22float2(*reinterpret_cast<const __half2*>(&raw.x));
            float2 f23 = __half22float2(*reinterpret_cast<const __half2*>(&raw.y));
            acc.x += f01.x * wj;
            acc.y += f01.y * wj;
            acc.z += f23.x * wj;
            acc.w += f23.y * wj;
        }
    } else {
        float s0 = 0.f, s1 = 0.f, s2 = 0.f, s3 = 0.f;
        for (int i = lane; i < deg; i += 32) {
            int s = g_col[base + i];
            float4 as = g_asrc[s];
            float p0 = expf(fminf(lrelu(as.x + ad.x), 75.f));
            float p1 = expf(fminf(lrelu(as.y + ad.y), 75.f));
            float p2 = expf(fminf(lrelu(as.z + ad.z), 75.f));
            float p3 = expf(fminf(lrelu(as.w + ad.w), 75.f));
            g_ew[base + i] = make_float4(p0, p1, p2, p3);
            s0 += p0; s1 += p1; s2 += p2; s3 += p3;
        }
        s0 = warp_sum(s0); s1 = warp_sum(s1); s2 = warp_sum(s2); s3 = warp_sum(s3);
        float i0 = 1.f / (s0 + 1e-10f);
        float i1 = 1.f / (s1 + 1e-10f);
        float i2 = 1.f / (s2 + 1e-10f);
        float i3 = 1.f / (s3 + 1e-10f);

        for (int bi = 0; bi < deg; bi += 32) {
            int cnt = min(32, deg - bi);
            if (lane < cnt) {
                sidx[w][lane] = g_col[base + bi + lane];
                float4 p = g_ew[base + bi + lane];
                swt[w][lane] = make_float4(p.x * i0, p.y * i1, p.z * i2, p.w * i3);
            }
            __syncwarp();
#pragma unroll 4
            for (int j = 0; j < cnt; j++) {
                int s = sidx[w][j];
                float wj = reinterpret_cast<const float*>(&swt[w][j])[hsel];
                uint2 raw = *reinterpret_cast<const uint2*>(&h[(size_t)s * 128 + 4 * lane]);
                float2 f01 = __half22float2(*reinterpret_cast<const __half2*>(&raw.x));
                float2 f23 = __half22float2(*reinterpret_cast<const __half2*>(&raw.y));
                acc.x += f01.x * wj;
                acc.y += f01.y * wj;
                acc.z += f23.x * wj;
                acc.w += f23.y * wj;
            }
            __syncwarp();
        }
    }

    size_t o = (size_t)gw * 128 + 4 * lane;
    float4 xp;
    if (xprev_f) {
        xp = *reinterpret_cast<const float4*>(&xprev_f[o]);
    } else {
        uint2 rh = *reinterpret_cast<const uint2*>(&xhi[o]);
        uint2 rl = *reinterpret_cast<const uint2*>(&xlo[o]);
        __nv_bfloat162 h0 = *reinterpret_cast<const __nv_bfloat162*>(&rh.x);
        __nv_bfloat162 h1 = *reinterpret_cast<const __nv_bfloat162*>(&rh.y);
        __nv_bfloat162 l0 = *reinterpret_cast<const __nv_bfloat162*>(&rl.x);
        __nv_bfloat162 l1 = *reinterpret_cast<const __nv_bfloat162*>(&rl.y);
        xp = make_float4(__bfloat162float(h0.x) + __bfloat162float(l0.x),
                         __bfloat162float(h0.y) + __bfloat162float(l0.y),
                         __bfloat162float(h1.x) + __bfloat162float(l1.x),
                         __bfloat162float(h1.y) + __bfloat162float(l1.y));
    }
    float4 v = make_float4(elu(acc.x) + xp.x, elu(acc.y) + xp.y,
                           elu(acc.z) + xp.z, elu(acc.w) + xp.w);
    {
        __nv_bfloat162 h0 = __floats2bfloat162_rn(v.x, v.y);
        __nv_bfloat162 h1 = __floats2bfloat162_rn(v.z, v.w);
        __nv_bfloat162 l0 = __floats2bfloat162_rn(v.x - __bfloat162float(h0.x), v.y - __bfloat162float(h0.y));
        __nv_bfloat162 l1 = __floats2bfloat162_rn(v.z - __bfloat162float(h1.x), v.w - __bfloat162float(h1.y));
        uint2 ph = make_uint2(*(uint32_t*)&h0, *(uint32_t*)&h1);
        uint2 pl = make_uint2(*(uint32_t*)&l0, *(uint32_t*)&l1);
        *reinterpret_cast<uint2*>(&xhi[o]) = ph;
        *reinterpret_cast<uint2*>(&xlo[o]) = pl;
    }
}

// ---------------- pair epilogue (fp16 u,v) ----------------
__global__ void k_pairs(const int* __restrict__ lsrc, const int* __restrict__ ldst,
                        const float* __restrict__ b1, const float* __restrict__ w2,
                        const float* __restrict__ b2, float* __restrict__ out, int p)
{
    int gw = (blockIdx.x * blockDim.x + threadIdx.x) >> 5;
    int lane = threadIdx.x & 31;
    if (gw >= p) return;
    int k = 4 * lane;
    uint2 ru = *reinterpret_cast<const uint2*>(&g_u[(size_t)lsrc[gw] * 128 + k]);
    uint2 rv = *reinterpret_cast<const uint2*>(&g_v[(size_t)ldst[gw] * 128 + k]);
    float2 u01 = __half22float2(*reinterpret_cast<const __half2*>(&ru.x));
    float2 u23 = __half22float2(*reinterpret_cast<const __half2*>(&ru.y));
    float2 v01 = __half22float2(*reinterpret_cast<const __half2*>(&rv.x));
    float2 v23 = __half22float2(*reinterpret_cast<const __half2*>(&rv.y));
    float4 b = *reinterpret_cast<const float4*>(&b1[k]);
    float4 w = *reinterpret_cast<const float4*>(&w2[k]);
    float t = fmaxf(u01.x + v01.x + b.x, 0.f) * w.x
            + fmaxf(u01.y + v01.y + b.y, 0.f) * w.y
            + fmaxf(u23.x + v23.x + b.z, 0.f) * w.z
            + fmaxf(u23.y + v23.y + b.w, 0.f) * w.w;
    t = warp_sum(t);
    if (lane == 0) out[gw] = t + b2[0];
}

// ---------------- driver ----------------
extern "C" void kernel_launch(void* const* d_in, const int* in_sizes, int n_in,
                              void* d_out, int out_size)
{
    const float* embed  = (const float*)d_in[0];
    const float* W1     = (const float*)d_in[1];
    const float* a_src1 = (const float*)d_in[2];
    const float* a_dst1 = (const float*)d_in[3];
    const float* W2     = (const float*)d_in[4];
    const float* a_src2 = (const float*)d_in[5];
    const float* a_dst2 = (const float*)d_in[6];
    const float* lp_w1  = (const float*)d_in[7];
    const float* lp_b1  = (const float*)d_in[8];
    const float* lp_w2  = (const float*)d_in[9];
    const float* lp_b2  = (const float*)d_in[10];
    const int*   eidx   = (const int*)d_in[11];
    const int*   lsrc   = (const int*)d_in[12];
    const int*   ldst   = (const int*)d_in[13];
    float* out = (float*)d_out;

    const int N = in_sizes[0] / DDIM;
    const int E = in_sizes[11] / 2;
    const int P = in_sizes[12];
    const int* esrc = eidx;
    const int* edst = eidx + E;

    __half* hbuf; cudaGetSymbolAddress((void**)&hbuf, g_h);
    __half* ub;   cudaGetSymbolAddress((void**)&ub,   g_u);
    __half* vb;   cudaGetSymbolAddress((void**)&vb,   g_v);
    __nv_bfloat16* ahi; cudaGetSymbolAddress((void**)&ahi, g_ahi);
    __nv_bfloat16* alo; cudaGetSymbolAddress((void**)&alo, g_alo);
    __nv_bfloat16* wthi; cudaGetSymbolAddress((void**)&wthi, g_wthi);
    __nv_bfloat16* wtlo; cudaGetSymbolAddress((void**)&wtlo, g_wtlo);

    cudaFuncSetAttribute(k_gemm_mma,  cudaFuncAttributeMaxDynamicSharedMemorySize, GEMM_SMEM);
    cudaFuncSetAttribute(k_gemm_mma2, cudaFuncAttributeMaxDynamicSharedMemorySize, GEMM2_SMEM);

    const int T = 256;
    int nbN  = (N + T - 1) / T;
    int nbE  = (E + T - 1) / T;
    int nbS  = (N + 1023) / 1024;
    int nbW  = (N * 32 + T - 1) / T;
    int nbPW = (P * 32 + T - 1) / T;
    int nbG  = (N + 127) / 128;
    const int WSZ = DDIM * DDIM;

    // setup + CSR; gemm1 placed at launch index 3 so ncu (-s 5, with the two
    // harness pre-launches) profiles it instead of a scan kernel.
    k_setup<<<nbN, T>>>(W1, W2, lp_w1, wthi, wtlo, N);      // 0
    k_hist<<<nbE, T>>>(edst, E);                            // 1
    k_scan1<<<nbS, 1024>>>(N);                              // 2
    k_gemm_mma<<<nbG, 512, GEMM_SMEM>>>(embed, nullptr, nullptr,   // 3
                                        wthi + 0 * WSZ, wtlo + 0 * WSZ, hbuf,
                                        a_src1, a_dst1, N);
    k_scan2<<<1, 128>>>(nbS);                               // 4
    k_scan3<<<nbS, 1024>>>(N, E);                           // 5
    k_scatter<<<nbE, T>>>(esrc, edst, E);                   // 6

    // layer 1 aggregation (writes ahi/alo = split of x2)
    k_edgeagg<<<nbW, T>>>(hbuf, embed, ahi, alo, N);        // 7

    // layer 2
    k_gemm_mma<<<nbG, 512, GEMM_SMEM>>>(nullptr, ahi, alo,  // 8
                                        wthi + 1 * WSZ, wtlo + 1 * WSZ, hbuf,
                                        a_src2, a_dst2, N);
    k_edgeagg<<<nbW, T>>>(hbuf, nullptr, ahi, alo, N);      // 9 (in-place residual)

    // link predictor
    k_gemm_mma2<<<nbG, 512, GEMM2_SMEM>>>(ahi, alo,         // 10
                                          wthi + 2 * WSZ, wtlo + 2 * WSZ,
                                          wthi + 3 * WSZ, wtlo + 3 * WSZ,
                                          ub, vb, N);
    k_pairs<<<nbPW, T>>>(lsrc, ldst, lp_b1, lp_w2, lp_b2, out, P);  // 11
}

// round 11
// speedup vs baseline: 1.0982x; 1.0039x over previous
#include <cuda_runtime.h>
#include <cuda_bf16.h>
#include <cuda_fp16.h>
#include <math.h>
#include <stdint.h>

#define NMAX 100000
#define EMAX 1600000
#define DDIM 128

// ---------------- scratch ----------------
__device__ __half g_h [NMAX * DDIM];
__device__ __half g_u [NMAX * DDIM];
__device__ __half g_v [NMAX * DDIM];
__device__ __nv_bfloat16 g_ahi[NMAX * DDIM];
__device__ __nv_bfloat16 g_alo[NMAX * DDIM];
__device__ __nv_bfloat16 g_wthi[4 * DDIM * DDIM];
__device__ __nv_bfloat16 g_wtlo[4 * DDIM * DDIM];
__device__ float4 g_asrc[NMAX];
__device__ float4 g_adst[NMAX];
__device__ float4 g_ew  [EMAX];
__device__ int g_deg   [NMAX];
__device__ int g_rowptr[NMAX + 1];
__device__ int g_cursor[NMAX];
__device__ int g_col   [EMAX];
__device__ int g_bsums [1024];

__device__ __forceinline__ uint32_t smem_to_u32(const void* p) {
    uint32_t a;
    asm("{ .reg .u64 t; cvta.to.shared.u64 t, %1; cvt.u32.u64 %0, t; }" : "=r"(a) : "l"(p));
    return a;
}
#define SW128(off) ((off) ^ (((off) >> 3) & 0x70))

#define LDSM4(r0, r1, r2, r3, addr) \
    asm volatile("ldmatrix.sync.aligned.m8n8.x4.shared.b16 {%0,%1,%2,%3}, [%4];" \
        : "=r"(r0), "=r"(r1), "=r"(r2), "=r"(r3) : "r"(addr))

__device__ __forceinline__ void mma16816(float* d, const uint32_t* a, const uint32_t* b) {
    asm volatile(
        "mma.sync.aligned.m16n8k16.row.col.f32.bf16.bf16.f32 "
        "{%0,%1,%2,%3},{%4,%5,%6,%7},{%8,%9},{%0,%1,%2,%3};"
        : "+f"(d[0]), "+f"(d[1]), "+f"(d[2]), "+f"(d[3])
        : "r"(a[0]), "r"(a[1]), "r"(a[2]), "r"(a[3]), "r"(b[0]), "r"(b[1]));
}

// ---------------- setup ----------------
__device__ __forceinline__ void wsplit_one(const float* __restrict__ W,
                                           __nv_bfloat16* __restrict__ hi,
                                           __nv_bfloat16* __restrict__ lo, int i) {
    int nn = i >> 6;
    int kp = (i & 63) * 2;
    float x0 = W[(size_t)kp * 128 + nn];
    float x1 = W[(size_t)(kp + 1) * 128 + nn];
    __nv_bfloat162 h = __floats2bfloat162_rn(x0, x1);
    float r0 = x0 - __bfloat162float(h.x);
    float r1 = x1 - __bfloat162float(h.y);
    __nv_bfloat162 l = __floats2bfloat162_rn(r0, r1);
    reinterpret_cast<__nv_bfloat162*>(hi)[i] = h;
    reinterpret_cast<__nv_bfloat162*>(lo)[i] = l;
}

__global__ void k_setup(const float* __restrict__ W1, const float* __restrict__ W2,
                        const float* __restrict__ lpw1,
                        __nv_bfloat16* __restrict__ wthi, __nv_bfloat16* __restrict__ wtlo,
                        int n) {
    const int WSZ = DDIM * DDIM;
    int i = blockIdx.x * blockDim.x + threadIdx.x;
    if (i < n) g_deg[i] = 0;
    if (i < 8192)       wsplit_one(W1,               wthi + 0 * WSZ, wtlo + 0 * WSZ, i);
    else if (i < 16384) wsplit_one(W2,               wthi + 1 * WSZ, wtlo + 1 * WSZ, i - 8192);
    else if (i < 24576) wsplit_one(lpw1,             wthi + 2 * WSZ, wtlo + 2 * WSZ, i - 16384);
    else if (i < 32768) wsplit_one(lpw1 + 128 * 128, wthi + 3 * WSZ, wtlo + 3 * WSZ, i - 24576);
}

// ---------------- CSR build ----------------
__global__ void k_hist(const int* __restrict__ dst, int e) {
    int i = blockIdx.x * blockDim.x + threadIdx.x;
    if (i < e) atomicAdd(&g_deg[dst[i]], 1);
}
__global__ void k_scan1(int n) {
    __shared__ int ws[32];
    int tid = threadIdx.x;
    int lane = tid & 31, w = tid >> 5;
    int i = blockIdx.x * 1024 + tid;
    int v = (i < n) ? g_deg[i] : 0;
    int x = v;
#pragma unroll
    for (int o = 1; o < 32; o <<= 1) {
        int t = __shfl_up_sync(0xffffffffu, x, o);
        if (lane >= o) x += t;
    }
    if (lane == 31) ws[w] = x;
    __syncthreads();
    if (w == 0) {
        int t = ws[lane];
        int s = t;
#pragma unroll
        for (int o = 1; o < 32; o <<= 1) {
            int q = __shfl_up_sync(0xffffffffu, s, o);
            if (lane >= o) s += q;
        }
        ws[lane] = s - t;
    }
    __syncthreads();
    int incl = x + ws[w];
    if (i < n) g_rowptr[i] = incl - v;
    if (tid == 1023) g_bsums[blockIdx.x] = incl;
}
__global__ void k_scan2(int nb) {
    __shared__ int wsum[4];
    int tid = threadIdx.x;
    int lane = tid & 31, w = tid >> 5;
    int v = (tid < nb) ? g_bsums[tid] : 0;
    int x = v;
#pragma unroll
    for (int o = 1; o < 32; o <<= 1) {
        int t = __shfl_up_sync(0xffffffffu, x, o);
        if (lane >= o) x += t;
    }
    if (lane == 31) wsum[w] = x;
    __syncthreads();
    int add = 0;
#pragma unroll
    for (int j = 0; j < 4; j++) add += (j < w) ? wsum[j] : 0;
    if (tid < nb) g_bsums[tid] = x - v + add;
}
__global__ void k_scan3(int n, int e) {
    int i = blockIdx.x * 1024 + threadIdx.x;
    if (i < n) {
        int v = g_rowptr[i] + g_bsums[blockIdx.x];
        g_rowptr[i] = v;
        g_cursor[i] = v;
    }
    if (i == 0) g_rowptr[n] = e;
}
__global__ void k_scatter(const int* __restrict__ src, const int* __restrict__ dst, int e) {
    int i = blockIdx.x * blockDim.x + threadIdx.x;
    if (i < e) {
        int d = dst[i];
        int slot = atomicAdd(&g_cursor[d], 1);
        g_col[slot] = src[i];
    }
}

// ---------------- HMMA GEMM, block 256x128, warp tile 64x32 ----------------
// smem: A hi/lo (2 x 64KB) + B hi/lo (2 x 32KB) = 192KB
#define GEMM_SMEM 196608

__global__ void __launch_bounds__(512, 1) k_gemm_mma(
    const float* __restrict__ Af,
    const __nv_bfloat16* __restrict__ Ahi, const __nv_bfloat16* __restrict__ Alo,
    const __nv_bfloat16* __restrict__ Bhi, const __nv_bfloat16* __restrict__ Blo,
    __half* __restrict__ C,
    const float* __restrict__ a_src, const float* __restrict__ a_dst, int n)
{
    extern __shared__ char smem[];
    __shared__ float sAl[256][4];
    __shared__ float sDl[256][4];
    uint32_t sb = smem_to_u32(smem);
    const uint32_t sAhi = sb;
    const uint32_t sAlo = sb + 65536;
    const uint32_t sBhi = sb + 131072;
    const uint32_t sBlo = sb + 163840;

    int tid = threadIdx.x;
    int wid = tid >> 5, lane = tid & 31;
    int wm = wid & 3, wn = wid >> 2;
    int row0 = blockIdx.x * 256;

    if (tid < 256) {
        *reinterpret_cast<float4*>(&sAl[tid][0]) = make_float4(0.f, 0.f, 0.f, 0.f);
        *reinterpret_cast<float4*>(&sDl[tid][0]) = make_float4(0.f, 0.f, 0.f, 0.f);
    }

    float acc[4][4][4];
#pragma unroll
    for (int i = 0; i < 4; i++)
#pragma unroll
        for (int j = 0; j < 4; j++)
#pragma unroll
            for (int q = 0; q < 4; q++) acc[i][j][q] = 0.f;

    const uint4 zero4 = make_uint4(0, 0, 0, 0);

    // ---- A: 256 rows, 2 K-halves -> 4096 uint4 per array ----
#pragma unroll
    for (int t = 0; t < 8; t++) {
        int i = tid + t * 512;
        int r = i >> 4;
        int o = i & 15;
        int kh = o >> 3, oo = o & 7;
        uint32_t soff = (uint32_t)(kh * 32768) + SW128((uint32_t)(r * 128 + oo * 16));
        size_t elem = (size_t)(row0 + r) * 128 + kh * 64 + oo * 8;
        bool av = (row0 + r) < n;
        uint4 va, vb;
        if (Af) {
            float4 f0 = make_float4(0.f, 0.f, 0.f, 0.f), f1 = f0;
            if (av) {
                f0 = *reinterpret_cast<const float4*>(&Af[elem]);
                f1 = *reinterpret_cast<const float4*>(&Af[elem + 4]);
            }
            __nv_bfloat162 h0 = __floats2bfloat162_rn(f0.x, f0.y);
            __nv_bfloat162 h1 = __floats2bfloat162_rn(f0.z, f0.w);
            __nv_bfloat162 h2 = __floats2bfloat162_rn(f1.x, f1.y);
            __nv_bfloat162 h3 = __floats2bfloat162_rn(f1.z, f1.w);
            __nv_bfloat162 l0 = __floats2bfloat162_rn(f0.x - __bfloat162float(h0.x), f0.y - __bfloat162float(h0.y));
            __nv_bfloat162 l1 = __floats2bfloat162_rn(f0.z - __bfloat162float(h1.x), f0.w - __bfloat162float(h1.y));
            __nv_bfloat162 l2 = __floats2bfloat162_rn(f1.x - __bfloat162float(h2.x), f1.y - __bfloat162float(h2.y));
            __nv_bfloat162 l3 = __floats2bfloat162_rn(f1.z - __bfloat162float(h3.x), f1.w - __bfloat162float(h3.y));
            va = make_uint4(*(uint32_t*)&h0, *(uint32_t*)&h1, *(uint32_t*)&h2, *(uint32_t*)&h3);
            vb = make_uint4(*(uint32_t*)&l0, *(uint32_t*)&l1, *(uint32_t*)&l2, *(uint32_t*)&l3);
        } else {
            va = av ? reinterpret_cast<const uint4*>(Ahi)[elem >> 3] : zero4;
            vb = av ? reinterpret_cast<const uint4*>(Alo)[elem >> 3] : zero4;
        }
        *reinterpret_cast<uint4*>(smem + (sAhi - sb) + soff) = va;
        *reinterpret_cast<uint4*>(smem + (sAlo - sb) + soff) = vb;
    }
    // ---- B: 128 n-rows, 2 K-halves -> 2048 uint4 per array ----
#pragma unroll
    for (int t = 0; t < 4; t++) {
        int i = tid + t * 512;
        int r = i >> 4;
        int o = i & 15;
        int kh = o >> 3, oo = o & 7;
        uint32_t soff = (uint32_t)(kh * 16384) + SW128((uint32_t)(r * 128 + oo * 16));
        size_t bidx = ((size_t)r * 128 + kh * 64 + oo * 8) >> 3;
        *reinterpret_cast<uint4*>(smem + (sBhi - sb) + soff) = reinterpret_cast<const uint4*>(Bhi)[bidx];
        *reinterpret_cast<uint4*>(smem + (sBlo - sb) + soff) = reinterpret_cast<const uint4*>(Blo)[bidx];
    }
    __syncthreads();

#pragma unroll
    for (int kh = 0; kh < 2; kh++) {
        uint32_t hoffA = (uint32_t)(kh * 32768);
        uint32_t hoffB = (uint32_t)(kh * 16384);
#pragma unroll
        for (int kk = 0; kk < 4; kk++) {
            int lr = lane & 15;
            int kin = kk * 16 + ((lane >> 4) << 3);
            uint32_t bxh[2][4], bxl[2][4];
#pragma unroll
            for (int nf = 0; nf < 2; nf++) {
                uint32_t off = hoffB + SW128((uint32_t)((wn * 32 + nf * 16 + lr) * 128 + kin * 2));
                LDSM4(bxh[nf][0], bxh[nf][1], bxh[nf][2], bxh[nf][3], sBhi + off);
                LDSM4(bxl[nf][0], bxl[nf][1], bxl[nf][2], bxl[nf][3], sBlo + off);
            }
#pragma unroll
            for (int mfg = 0; mfg < 2; mfg++) {
                uint32_t ahi[2][4], alo[2][4];
#pragma unroll
                for (int mh = 0; mh < 2; mh++) {
                    int mf = mfg * 2 + mh;
                    uint32_t off = hoffA + SW128((uint32_t)((wm * 64 + mf * 16 + lr) * 128 + kin * 2));
                    LDSM4(ahi[mh][0], ahi[mh][1], ahi[mh][2], ahi[mh][3], sAhi + off);
                    LDSM4(alo[mh][0], alo[mh][1], alo[mh][2], alo[mh][3], sAlo + off);
                }
#pragma unroll
                for (int mh = 0; mh < 2; mh++) {
#pragma unroll
                    for (int ns = 0; ns < 4; ns++) {
                        int g = ns >> 1, od = ns & 1;
                        uint32_t bh[2] = { bxh[g][od], bxh[g][od + 2] };
                        uint32_t bl[2] = { bxl[g][od], bxl[g][od + 2] };
                        float* a = acc[mfg * 2 + mh][ns];
                        mma16816(a, ahi[mh], bh);
                        mma16816(a, ahi[mh], bl);
                        mma16816(a, alo[mh], bh);
                    }
                }
            }
        }
    }

    int qrow = lane >> 2, qcol = (lane & 3) * 2;

    // fused alpha partial dots
    {
        float2 s2[4], d2[4];
#pragma unroll
        for (int ns = 0; ns < 4; ns++) {
            int c = wn * 32 + ns * 8 + qcol;
            s2[ns] = *reinterpret_cast<const float2*>(&a_src[c]);
            d2[ns] = *reinterpret_cast<const float2*>(&a_dst[c]);
        }
#pragma unroll
        for (int mf = 0; mf < 4; mf++) {
            int rl = wm * 64 + mf * 16 + qrow;
            float pa0 = 0.f, pd0 = 0.f, pa1 = 0.f, pd1 = 0.f;
#pragma unroll
            for (int ns = 0; ns < 4; ns++) {
                pa0 += acc[mf][ns][0] * s2[ns].x + acc[mf][ns][1] * s2[ns].y;
                pd0 += acc[mf][ns][0] * d2[ns].x + acc[mf][ns][1] * d2[ns].y;
                pa1 += acc[mf][ns][2] * s2[ns].x + acc[mf][ns][3] * s2[ns].y;
                pd1 += acc[mf][ns][2] * d2[ns].x + acc[mf][ns][3] * d2[ns].y;
            }
            atomicAdd(&sAl[rl][wn], pa0);     atomicAdd(&sDl[rl][wn], pd0);
            atomicAdd(&sAl[rl + 8][wn], pa1); atomicAdd(&sDl[rl + 8][wn], pd1);
        }
    }

    // h store as fp16
#pragma unroll
    for (int mf = 0; mf < 4; mf++) {
#pragma unroll
        for (int ns = 0; ns < 4; ns++) {
            int r0 = row0 + wm * 64 + mf * 16 + qrow;
            int c0 = wn * 32 + ns * 8 + qcol;
            if (r0 < n) {
                __half2 hv = __floats2half2_rn(acc[mf][ns][0], acc[mf][ns][1]);
                *reinterpret_cast<uint32_t*>(&C[(size_t)r0 * 128 + c0]) = *(uint32_t*)&hv;
            }
            if (r0 + 8 < n) {
                __half2 hv = __floats2half2_rn(acc[mf][ns][2], acc[mf][ns][3]);
                *reinterpret_cast<uint32_t*>(&C[(size_t)(r0 + 8) * 128 + c0]) = *(uint32_t*)&hv;
            }
        }
    }

    __syncthreads();
    if (tid < 256 && row0 + tid < n) {
        g_asrc[row0 + tid] = *reinterpret_cast<float4*>(&sAl[tid][0]);
        g_adst[row0 + tid] = *reinterpret_cast<float4*>(&sDl[tid][0]);
    }
}

// ---------------- dual-B GEMM: A loaded once, B1/B2 sequential ----------------
#define GEMM2_SMEM 196608

__global__ void __launch_bounds__(512, 1) k_gemm_mma2(
    const __nv_bfloat16* __restrict__ Ahi, const __nv_bfloat16* __restrict__ Alo,
    const __nv_bfloat16* __restrict__ B1hi, const __nv_bfloat16* __restrict__ B1lo,
    const __nv_bfloat16* __restrict__ B2hi, const __nv_bfloat16* __restrict__ B2lo,
    __half* __restrict__ C1, __half* __restrict__ C2, int n)
{
    extern __shared__ char smem[];
    uint32_t sb = smem_to_u32(smem);
    const uint32_t sAhi = sb;
    const uint32_t sAlo = sb + 65536;
    const uint32_t sBhi = sb + 131072;
    const uint32_t sBlo = sb + 163840;

    int tid = threadIdx.x;
    int wid = tid >> 5, lane = tid & 31;
    int wm = wid & 3, wn = wid >> 2;
    int row0 = blockIdx.x * 256;

    const uint4 zero4 = make_uint4(0, 0, 0, 0);

    // A once
#pragma unroll
    for (int t = 0; t < 8; t++) {
        int i = tid + t * 512;
        int r = i >> 4;
        int o = i & 15;
        int kh = o >> 3, oo = o & 7;
        uint32_t soff = (uint32_t)(kh * 32768) + SW128((uint32_t)(r * 128 + oo * 16));
        size_t elem = (size_t)(row0 + r) * 128 + kh * 64 + oo * 8;
        bool av = (row0 + r) < n;
        uint4 va = av ? reinterpret_cast<const uint4*>(Ahi)[elem >> 3] : zero4;
        uint4 vb = av ? reinterpret_cast<const uint4*>(Alo)[elem >> 3] : zero4;
        *reinterpret_cast<uint4*>(smem + (sAhi - sb) + soff) = va;
        *reinterpret_cast<uint4*>(smem + (sAlo - sb) + soff) = vb;
    }

    for (int g = 0; g < 2; g++) {
        const __nv_bfloat16* Bh = g ? B2hi : B1hi;
        const __nv_bfloat16* Bl = g ? B2lo : B1lo;
        __half* C = g ? C2 : C1;

#pragma unroll
        for (int t = 0; t < 4; t++) {
            int i = tid + t * 512;
            int r = i >> 4;
            int o = i & 15;
            int kh = o >> 3, oo = o & 7;
            uint32_t soff = (uint32_t)(kh * 16384) + SW128((uint32_t)(r * 128 + oo * 16));
            size_t bidx = ((size_t)r * 128 + kh * 64 + oo * 8) >> 3;
            *reinterpret_cast<uint4*>(smem + (sBhi - sb) + soff) = reinterpret_cast<const uint4*>(Bh)[bidx];
            *reinterpret_cast<uint4*>(smem + (sBlo - sb) + soff) = reinterpret_cast<const uint4*>(Bl)[bidx];
        }
        __syncthreads();

        float acc[4][4][4];
#pragma unroll
        for (int i = 0; i < 4; i++)
#pragma unroll
            for (int j = 0; j < 4; j++)
#pragma unroll
                for (int q = 0; q < 4; q++) acc[i][j][q] = 0.f;

#pragma unroll
        for (int kh = 0; kh < 2; kh++) {
            uint32_t hoffA = (uint32_t)(kh * 32768);
            uint32_t hoffB = (uint32_t)(kh * 16384);
#pragma unroll
            for (int kk = 0; kk < 4; kk++) {
                int lr = lane & 15;
                int kin = kk * 16 + ((lane >> 4) << 3);
                uint32_t bxh[2][4], bxl[2][4];
#pragma unroll
                for (int nf = 0; nf < 2; nf++) {
                    uint32_t off = hoffB + SW128((uint32_t)((wn * 32 + nf * 16 + lr) * 128 + kin * 2));
                    LDSM4(bxh[nf][0], bxh[nf][1], bxh[nf][2], bxh[nf][3], sBhi + off);
                    LDSM4(bxl[nf][0], bxl[nf][1], bxl[nf][2], bxl[nf][3], sBlo + off);
                }
#pragma unroll
                for (int mfg = 0; mfg < 2; mfg++) {
                    uint32_t ahi[2][4], alo[2][4];
#pragma unroll
                    for (int mh = 0; mh < 2; mh++) {
                        int mf = mfg * 2 + mh;
                        uint32_t off = hoffA + SW128((uint32_t)((wm * 64 + mf * 16 + lr) * 128 + kin * 2));
                        LDSM4(ahi[mh][0], ahi[mh][1], ahi[mh][2], ahi[mh][3], sAhi + off);
                        LDSM4(alo[mh][0], alo[mh][1], alo[mh][2], alo[mh][3], sAlo + off);
                    }
#pragma unroll
                    for (int mh = 0; mh < 2; mh++) {
#pragma unroll
                        for (int ns = 0; ns < 4; ns++) {
                            int gg = ns >> 1, od = ns & 1;
                            uint32_t bh[2] = { bxh[gg][od], bxh[gg][od + 2] };
                            uint32_t bl[2] = { bxl[gg][od], bxl[gg][od + 2] };
                            float* a = acc[mfg * 2 + mh][ns];
                            mma16816(a, ahi[mh], bh);
                            mma16816(a, ahi[mh], bl);
                            mma16816(a, alo[mh], bh);
                        }
                    }
                }
            }
        }

        int qrow = lane >> 2, qcol = (lane & 3) * 2;
#pragma unroll
        for (int mf = 0; mf < 4; mf++) {
#pragma unroll
            for (int ns = 0; ns < 4; ns++) {
                int r0 = row0 + wm * 64 + mf * 16 + qrow;
                int c0 = wn * 32 + ns * 8 + qcol;
                if (r0 < n) {
                    __half2 hv = __floats2half2_rn(acc[mf][ns][0], acc[mf][ns][1]);
                    *reinterpret_cast<uint32_t*>(&C[(size_t)r0 * 128 + c0]) = *(uint32_t*)&hv;
                }
                if (r0 + 8 < n) {
                    __half2 hv = __floats2half2_rn(acc[mf][ns][2], acc[mf][ns][3]);
                    *reinterpret_cast<uint32_t*>(&C[(size_t)(r0 + 8) * 128 + c0]) = *(uint32_t*)&hv;
                }
            }
        }
        __syncthreads();   // B reload safety for next g
    }
}

// ---------------- warp helpers ----------------
__device__ __forceinline__ float warp_sum(float v) {
#pragma unroll
    for (int o = 16; o; o >>= 1) v += __shfl_xor_sync(0xffffffffu, v, o);
    return v;
}

__device__ __forceinline__ float lrelu(float x) { return x >= 0.f ? x : 0.2f * x; }
__device__ __forceinline__ float elu(float x)  { return x > 0.f ? x : expm1f(x); }

// ---------------- fused GAT aggregation ----------------
__global__ void k_edgeagg(const __half* __restrict__ h,
                          const float* __restrict__ xprev_f,
                          __nv_bfloat16* __restrict__ xhi,
                          __nv_bfloat16* __restrict__ xlo, int n)
{
    __shared__ int   sidx[8][32];
    __shared__ float4 swt[8][32];

    int w = threadIdx.x >> 5;
    int gw = (blockIdx.x * blockDim.x + threadIdx.x) >> 5;
    int lane = threadIdx.x & 31;
    if (gw >= n) return;

    int base = g_rowptr[gw];
    int deg  = g_rowptr[gw + 1] - base;
    float4 ad = g_adst[gw];
    float4 acc = make_float4(0.f, 0.f, 0.f, 0.f);
    int hsel = lane >> 3;

    if (deg <= 32) {
        int myidx = 0;
        float p0 = 0.f, p1 = 0.f, p2 = 0.f, p3 = 0.f;
        if (lane < deg) {
            myidx = g_col[base + lane];
            float4 as = g_asrc[myidx];
            p0 = expf(fminf(lrelu(as.x + ad.x), 75.f));
            p1 = expf(fminf(lrelu(as.y + ad.y), 75.f));
            p2 = expf(fminf(lrelu(as.z + ad.z), 75.f));
            p3 = expf(fminf(lrelu(as.w + ad.w), 75.f));
        }
        float i0 = 1.f / (warp_sum(p0) + 1e-10f);
        float i1 = 1.f / (warp_sum(p1) + 1e-10f);
        float i2 = 1.f / (warp_sum(p2) + 1e-10f);
        float i3 = 1.f / (warp_sum(p3) + 1e-10f);
        sidx[w][lane] = myidx;
        swt[w][lane] = make_float4(p0 * i0, p1 * i1, p2 * i2, p3 * i3);
        __syncwarp();
#pragma unroll 4
        for (int j = 0; j < deg; j++) {
            int s = sidx[w][j];
            float wj = reinterpret_cast<const float*>(&swt[w][j])[hsel];
            uint2 raw = *reinterpret_cast<const uint2*>(&h[(size_t)s * 128 + 4 * lane]);
            float2 f01 = __half22float2(*reinterpret_cast<const __half2*>(&raw.x));
            float2 f23 = __half22float2(*reinterpret_cast<const __half2*>(&raw.y));
            acc.x += f01.x * wj;
            acc.y += f01.y * wj;
            acc.z += f23.x * wj;
            acc.w += f23.y * wj;
        }
    } else {
        float s0 = 0.f, s1 = 0.f, s2 = 0.f, s3 = 0.f;
        for (int i = lane; i < deg; i += 32) {
            int s = g_col[base + i];
            float4 as = g_asrc[s];
            float p0 = expf(fminf(lrelu(as.x + ad.x), 75.f));
            float p1 = expf(fminf(lrelu(as.y + ad.y), 75.f));
            float p2 = expf(fminf(lrelu(as.z + ad.z), 75.f));
            float p3 = expf(fminf(lrelu(as.w + ad.w), 75.f));
            g_ew[base + i] = make_float4(p0, p1, p2, p3);
            s0 += p0; s1 += p1; s2 += p2; s3 += p3;
        }
        s0 = warp_sum(s0); s1 = warp_sum(s1); s2 = warp_sum(s2); s3 = warp_sum(s3);
        float i0 = 1.f / (s0 + 1e-10f);
        float i1 = 1.f / (s1 + 1e-10f);
        float i2 = 1.f / (s2 + 1e-10f);
        float i3 = 1.f / (s3 + 1e-10f);

        for (int bi = 0; bi < deg; bi += 32) {
            int cnt = min(32, deg - bi);
            if (lane < cnt) {
                sidx[w][lane] = g_col[base + bi + lane];
                float4 p = g_ew[base + bi + lane];
                swt[w][lane] = make_float4(p.x * i0, p.y * i1, p.z * i2, p.w * i3);
            }
            __syncwarp();
#pragma unroll 4
            for (int j = 0; j < cnt; j++) {
                int s = sidx[w][j];
                float wj = reinterpret_cast<const float*>(&swt[w][j])[hsel];
                uint2 raw = *reinterpret_cast<const uint2*>(&h[(size_t)s * 128 + 4 * lane]);
                float2 f01 = __half22float2(*reinterpret_cast<const __half2*>(&raw.x));
                float2 f23 = __half22float2(*reinterpret_cast<const __half2*>(&raw.y));
                acc.x += f01.x * wj;
                acc.y += f01.y * wj;
                acc.z += f23.x * wj;
                acc.w += f23.y * wj;
            }
            __syncwarp();
        }
    }

    size_t o = (size_t)gw * 128 + 4 * lane;
    float4 xp;
    if (xprev_f) {
        xp = *reinterpret_cast<const float4*>(&xprev_f[o]);
    } else {
        uint2 rh = *reinterpret_cast<const uint2*>(&xhi[o]);
        uint2 rl = *reinterpret_cast<const uint2*>(&xlo[o]);
        __nv_bfloat162 h0 = *reinterpret_cast<const __nv_bfloat162*>(&rh.x);
        __nv_bfloat162 h1 = *reinterpret_cast<const __nv_bfloat162*>(&rh.y);
        __nv_bfloat162 l0 = *reinterpret_cast<const __nv_bfloat162*>(&rl.x);
        __nv_bfloat162 l1 = *reinterpret_cast<const __nv_bfloat162*>(&rl.y);
        xp = make_float4(__bfloat162float(h0.x) + __bfloat162float(l0.x),
                         __bfloat162float(h0.y) + __bfloat162float(l0.y),
                         __bfloat162float(h1.x) + __bfloat162float(l1.x),
                         __bfloat162float(h1.y) + __bfloat162float(l1.y));
    }
    float4 v = make_float4(elu(acc.x) + xp.x, elu(acc.y) + xp.y,
                           elu(acc.z) + xp.z, elu(acc.w) + xp.w);
    {
        __nv_bfloat162 h0 = __floats2bfloat162_rn(v.x, v.y);
        __nv_bfloat162 h1 = __floats2bfloat162_rn(v.z, v.w);
        __nv_bfloat162 l0 = __floats2bfloat162_rn(v.x - __bfloat162float(h0.x), v.y - __bfloat162float(h0.y));
        __nv_bfloat162 l1 = __floats2bfloat162_rn(v.z - __bfloat162float(h1.x), v.w - __bfloat162float(h1.y));
        uint2 ph = make_uint2(*(uint32_t*)&h0, *(uint32_t*)&h1);
        uint2 pl = make_uint2(*(uint32_t*)&l0, *(uint32_t*)&l1);
        *reinterpret_cast<uint2*>(&xhi[o]) = ph;
        *reinterpret_cast<uint2*>(&xlo[o]) = pl;
    }
}

// ---------------- pair epilogue ----------------
__global__ void k_pairs(const int* __restrict__ lsrc, const int* __restrict__ ldst,
                        const float* __restrict__ b1, const float* __restrict__ w2,
                        const float* __restrict__ b2, float* __restrict__ out, int p)
{
    int gw = (blockIdx.x * blockDim.x + threadIdx.x) >> 5;
    int lane = threadIdx.x & 31;
    if (gw >= p) return;
    int k = 4 * lane;
    uint2 ru = *reinterpret_cast<const uint2*>(&g_u[(size_t)lsrc[gw] * 128 + k]);
    uint2 rv = *reinterpret_cast<const uint2*>(&g_v[(size_t)ldst[gw] * 128 + k]);
    float2 u01 = __half22float2(*reinterpret_cast<const __half2*>(&ru.x));
    float2 u23 = __half22float2(*reinterpret_cast<const __half2*>(&ru.y));
    float2 v01 = __half22float2(*reinterpret_cast<const __half2*>(&rv.x));
    float2 v23 = __half22float2(*reinterpret_cast<const __half2*>(&rv.y));
    float4 b = *reinterpret_cast<const float4*>(&b1[k]);
    float4 w = *reinterpret_cast<const float4*>(&w2[k]);
    float t = fmaxf(u01.x + v01.x + b.x, 0.f) * w.x
            + fmaxf(u01.y + v01.y + b.y, 0.f) * w.y
            + fmaxf(u23.x + v23.x + b.z, 0.f) * w.z
            + fmaxf(u23.y + v23.y + b.w, 0.f) * w.w;
    t = warp_sum(t);
    if (lane == 0) out[gw] = t + b2[0];
}

// ---------------- driver ----------------
extern "C" void kernel_launch(void* const* d_in, const int* in_sizes, int n_in,
                              void* d_out, int out_size)
{
    const float* embed  = (const float*)d_in[0];
    const float* W1     = (const float*)d_in[1];
    const float* a_src1 = (const float*)d_in[2];
    const float* a_dst1 = (const float*)d_in[3];
    const float* W2     = (const float*)d_in[4];
    const float* a_src2 = (const float*)d_in[5];
    const float* a_dst2 = (const float*)d_in[6];
    const float* lp_w1  = (const float*)d_in[7];
    const float* lp_b1  = (const float*)d_in[8];
    const float* lp_w2  = (const float*)d_in[9];
    const float* lp_b2  = (const float*)d_in[10];
    const int*   eidx   = (const int*)d_in[11];
    const int*   lsrc   = (const int*)d_in[12];
    const int*   ldst   = (const int*)d_in[13];
    float* out = (float*)d_out;

    const int N = in_sizes[0] / DDIM;
    const int E = in_sizes[11] / 2;
    const int P = in_sizes[12];
    const int* esrc = eidx;
    const int* edst = eidx + E;

    __half* hbuf; cudaGetSymbolAddress((void**)&hbuf, g_h);
    __half* ub;   cudaGetSymbolAddress((void**)&ub,   g_u);
    __half* vb;   cudaGetSymbolAddress((void**)&vb,   g_v);
    __nv_bfloat16* ahi; cudaGetSymbolAddress((void**)&ahi, g_ahi);
    __nv_bfloat16* alo; cudaGetSymbolAddress((void**)&alo, g_alo);
    __nv_bfloat16* wthi; cudaGetSymbolAddress((void**)&wthi, g_wthi);
    __nv_bfloat16* wtlo; cudaGetSymbolAddress((void**)&wtlo, g_wtlo);

    cudaFuncSetAttribute(k_gemm_mma,  cudaFuncAttributeMaxDynamicSharedMemorySize, GEMM_SMEM);
    cudaFuncSetAttribute(k_gemm_mma2, cudaFuncAttributeMaxDynamicSharedMemorySize, GEMM2_SMEM);

    const int T = 256;
    int nbN  = (N + T - 1) / T;
    int nbE  = (E + T - 1) / T;
    int nbS  = (N + 1023) / 1024;
    int nbW  = (N * 32 + T - 1) / T;
    int nbPW = (P * 32 + T - 1) / T;
    int nbG  = (N + 255) / 256;
    const int WSZ = DDIM * DDIM;

    k_setup<<<nbN, T>>>(W1, W2, lp_w1, wthi, wtlo, N);      // 0
    k_hist<<<nbE, T>>>(edst, E);                            // 1
    k_scan1<<<nbS, 1024>>>(N);                              // 2
    k_gemm_mma<<<nbG, 512, GEMM_SMEM>>>(embed, nullptr, nullptr,   // 3 (profiled)
                                        wthi + 0 * WSZ, wtlo + 0 * WSZ, hbuf,
                                        a_src1, a_dst1, N);
    k_scan2<<<1, 128>>>(nbS);                               // 4
    k_scan3<<<nbS, 1024>>>(N, E);                           // 5
    k_scatter<<<nbE, T>>>(esrc, edst, E);                   // 6

    k_edgeagg<<<nbW, T>>>(hbuf, embed, ahi, alo, N);        // 7

    k_gemm_mma<<<nbG, 512, GEMM_SMEM>>>(nullptr, ahi, alo,  // 8
                                        wthi + 1 * WSZ, wtlo + 1 * WSZ, hbuf,
                                        a_src2, a_dst2, N);
    k_edgeagg<<<nbW, T>>>(hbuf, nullptr, ahi, alo, N);      // 9

    k_gemm_mma2<<<nbG, 512, GEMM2_SMEM>>>(ahi, alo,         // 10
                                          wthi + 2 * WSZ, wtlo + 2 * WSZ,
                                          wthi + 3 * WSZ, wtlo + 3 * WSZ,
                                          ub, vb, N);
    k_pairs<<<nbPW, T>>>(lsrc, ldst, lp_b1, lp_w2, lp_b2, out, P);  // 11
}